// round 1
// baseline (speedup 1.0000x reference)
#include <cuda_runtime.h>
#include <math.h>

#define Bb 256
#define Nn 1024
#define Dd 64
#define NPAIR_SEQ 512              // N/2 pairs per sequence
#define TILE_P 128
#define NTILES 1024                // (Bb*Nn/2)/TILE_P
#define THREADS 512
#define SXS 129                    // padded row stride for sX

// output buffer offsets (floats)
#define LOFF 0
#define POFF (Bb*11*Nn)                  // losses: (B,11,N)
#define NOFF (POFF + Bb*Nn*11*2)         // preds:  (B,N,11,2) ; norms: (B,11,N)

// dynamic smem layout (floats)
#define SW1_OFF 0                        // 128x128 = 16384
#define SW2_OFF 16384                    // 2x64x64 = 8192
#define SX_OFF  (16384 + 8192)           // 128x129 = 16512
#define SB1_OFF (SX_OFF + TILE_P*SXS)
#define SB2_OFF (SB1_OFF + 128)
#define SC_OFF  (SB2_OFF + 128)
#define SLW_OFF (SC_OFF + 128)
#define SLB_OFF (SLW_OFF + 128)
#define SVX_OFF (SLB_OFF + 2)
#define SVE_OFF (SVX_OFF + 128)
#define SMEM_FLOATS (SVE_OFF + 128)
#define SMEM_BYTES (SMEM_FLOATS * 4)

__device__ float g_eA[Bb*Nn*Dd];
__device__ float g_eB[Bb*Nn*Dd];
__device__ int   g_vA[Bb*Nn];
__device__ int   g_vB[Bb*Nn];

// ---------------------------------------------------------------------------
// Stage 0: e0 = y @ emb_W + emb_b ; pred/loss/norm at stage index 0
// ---------------------------------------------------------------------------
__global__ void stage0_kernel(const int* __restrict__ x, const float* __restrict__ y,
                              const float* __restrict__ embW, const float* __restrict__ embB,
                              const float* __restrict__ llrW, const float* __restrict__ llrb,
                              float* __restrict__ e0, float* __restrict__ out)
{
    __shared__ float sE[128*65];
    __shared__ float sWe[128], sBe[64], sLW[128], sLB[2];
    const int tid = threadIdx.x;
    if (tid < 128) sWe[tid] = embW[tid];
    if (tid < 64)  sBe[tid] = embB[tid];
    if (tid < 128) sLW[tid] = llrW[tid];
    if (tid < 2)   sLB[tid] = llrb[tid];
    __syncthreads();

    const int gi = blockIdx.x * 128 + tid;          // global element 0..B*N-1
    const int b  = gi >> 10;
    const int n0 = gi & 1023;
    const float y0 = y[2*gi], y1 = y[2*gi+1];

    float ss = 0.f, l0 = sLB[0], l1 = sLB[1];
    #pragma unroll 8
    for (int d = 0; d < 64; d++) {
        float e = fmaf(y0, sWe[d], fmaf(y1, sWe[64+d], sBe[d]));
        ss = fmaf(e, e, ss);
        l0 = fmaf(e, sLW[2*d], l0);
        l1 = fmaf(e, sLW[2*d+1], l1);
        sE[tid*65 + d] = e;
    }
    // 2-class softmax + scce + norm, stage t=0
    float m = fmaxf(l0, l1);
    float x0 = expf(l0 - m), x1 = expf(l1 - m);
    float inv = 1.f / (x0 + x1);
    float p0 = x0 * inv, p1 = x1 * inv;
    int vv = x[gi];
    float pt = vv ? p1 : p0;
    pt = fminf(fmaxf(pt, 1e-7f), 1.0f);
    out[LOFF + (b*11 + 0)*Nn + n0] = -logf(pt);
    float* po = out + POFF + (((size_t)(b*Nn + n0))*11 + 0)*2;
    po[0] = p0; po[1] = p1;
    out[NOFF + (b*11 + 0)*Nn + n0] = sqrtf(ss);
    __syncthreads();

    // coalesced copy of e tile to global
    float4* dst = (float4*)(e0 + (size_t)blockIdx.x * 128 * 64);
    for (int i = tid; i < 128*16; i += 128) {
        int row = i >> 4, q = i & 15;
        const float* r = sE + row*65 + q*4;
        dst[i] = make_float4(r[0], r[1], r[2], r[3]);
    }
}

// ---------------------------------------------------------------------------
// One butterfly stage: gather pairs, fused 2-MLP GEMMs, epilogue outputs
// ---------------------------------------------------------------------------
__global__ void __launch_bounds__(THREADS, 1)
iter_kernel(const float* __restrict__ e_cur, const int* __restrict__ v_cur,
            float* __restrict__ e_next, int* __restrict__ v_next,
            const float* __restrict__ cnW1, const float* __restrict__ cnb1,
            const float* __restrict__ cnW2, const float* __restrict__ cnb2,
            const float* __restrict__ bnW1, const float* __restrict__ bnb1,
            const float* __restrict__ bnW2, const float* __restrict__ bnb2,
            const float* __restrict__ lab,  const float* __restrict__ llrW,
            const float* __restrict__ llrb, float* __restrict__ out, int t)
{
    extern __shared__ float sm[];
    float* sW1 = sm + SW1_OFF;
    float* sW2 = sm + SW2_OFF;
    float* sX  = sm + SX_OFF;
    float* sB1 = sm + SB1_OFF;
    float* sB2 = sm + SB2_OFF;
    float* sC  = sm + SC_OFF;
    float* sLW = sm + SLW_OFF;
    float* sLB = sm + SLB_OFF;
    int* sVx   = (int*)(sm + SVX_OFF);
    int* sVe   = (int*)(sm + SVE_OFF);

    const int tid = threadIdx.x;
    const int tx  = tid & 15;        // feature group (16 groups)
    const int ty  = tid >> 4;        // pair group (32 groups x 4 pairs)

    // ---- stage weights into smem (amortized over tiles) ----
    for (int i = tid; i < 16384; i += THREADS) {
        int k = i >> 7, f = i & 127;
        sW1[i] = (f < 64) ? cnW1[k*64 + f] : bnW1[k*64 + (f - 64)];
    }
    for (int i = tid; i < 4096; i += THREADS) sW2[i]        = cnW2[i];
    for (int i = tid; i < 4096; i += THREADS) sW2[4096 + i] = bnW2[i];
    if (tid < 128) {
        sB1[tid] = (tid < 64) ? cnb1[tid] : bnb1[tid - 64];
        sB2[tid] = (tid < 64) ? cnb2[tid] : bnb2[tid - 64];
        sLW[tid] = llrW[tid];
    }
    if (tid < 2) sLB[tid] = llrb[tid];
    if (tid < 128) {                 // c_j[f] = lab_emb[j] @ bn_W1[128:192, f]
        int jj = tid >> 6, f = tid & 63;
        float s = 0.f;
        for (int k = 0; k < 64; k++) s = fmaf(lab[jj*64 + k], bnW1[(128 + k)*64 + f], s);
        sC[jj*64 + f] = s;
    }

    const int scope = 1 << t;
    const int half  = scope >> 1;
    const int shl   = t - 1;          // pp >> shl = block index
    const int jmask = half - 1;

    for (int tile = blockIdx.x; tile < NTILES; tile += gridDim.x) {
        const int pg0 = tile * TILE_P;
        const int b   = pg0 >> 9;               // 512 pairs per sequence
        const int pp0 = pg0 & 511;
        __syncthreads();                        // weights ready / prev tile sX reads done

        // ---- gather X tile: rows = pair*2+side, 64 floats each ----
        const float* eb = e_cur + (size_t)b * (Nn * 64);
        for (int i = tid; i < TILE_P * 32; i += THREADS) {   // 4096 float4
            int row = i >> 4, q = i & 15;
            int p = row >> 1, side = row & 1;
            int pp = pp0 + p;
            int oddn = ((pp >> shl) << t) + (pp & jmask);
            int n = oddn + side * half;
            float4 v4 = *(const float4*)(eb + (size_t)n * 64 + q * 4);
            float* d = sX + p * SXS + side * 64 + q * 4;
            d[0]=v4.x; d[1]=v4.y; d[2]=v4.z; d[3]=v4.w;
        }
        if (tid < TILE_P) {
            int pp = pp0 + tid;
            int oddn = ((pp >> shl) << t) + (pp & jmask);
            int vo = v_cur[b*Nn + oddn];
            int ve = v_cur[b*Nn + oddn + half];
            sVx[tid] = (vo + ve) & 1;
            sVe[tid] = ve;
        }
        __syncthreads();

        // ---- GEMM1: H[128p x 128f] = X[128p x 128] @ W1cat ----
        float acc[4][8];
        #pragma unroll
        for (int i = 0; i < 4; i++)
            #pragma unroll
            for (int j = 0; j < 8; j++) acc[i][j] = 0.f;

        const float* sXrow = sX + (ty * 4) * SXS;
        #pragma unroll 4
        for (int k = 0; k < 128; k++) {
            float xv[4];
            #pragma unroll
            for (int i = 0; i < 4; i++) xv[i] = sXrow[i*SXS + k];
            #pragma unroll
            for (int j = 0; j < 8; j++) {
                float w = sW1[k*128 + tx + 16*j];
                #pragma unroll
                for (int i = 0; i < 4; i++) acc[i][j] = fmaf(xv[i], w, acc[i][j]);
            }
        }
        __syncthreads();
        // bias + c_vx + relu, H overwrites X in smem
        #pragma unroll
        for (int i = 0; i < 4; i++) {
            int p = ty*4 + i;
            int vx = sVx[p];
            #pragma unroll
            for (int j = 0; j < 8; j++) {
                int f = tx + 16*j;
                float h = acc[i][j] + sB1[f];
                if (j >= 4) h += sC[vx*64 + (f - 64)];
                sX[p*SXS + f] = fmaxf(h, 0.f);
            }
        }
        __syncthreads();

        // ---- GEMM2: out_l = Hl @ cnW2 ; out_r = Hr @ bnW2 ----
        #pragma unroll
        for (int i = 0; i < 4; i++)
            #pragma unroll
            for (int j = 0; j < 8; j++) acc[i][j] = 0.f;

        #pragma unroll 4
        for (int k = 0; k < 64; k++) {
            float xl[4], xr[4];
            #pragma unroll
            for (int i = 0; i < 4; i++) {
                xl[i] = sXrow[i*SXS + k];
                xr[i] = sXrow[i*SXS + 64 + k];
            }
            #pragma unroll
            for (int j = 0; j < 4; j++) {
                float w = sW2[k*64 + tx + 16*j];
                #pragma unroll
                for (int i = 0; i < 4; i++) acc[i][j] = fmaf(xl[i], w, acc[i][j]);
            }
            #pragma unroll
            for (int j = 4; j < 8; j++) {
                float w = sW2[4096 + k*64 + tx + 16*j - 64];
                #pragma unroll
                for (int i = 0; i < 4; i++) acc[i][j] = fmaf(xr[i], w, acc[i][j]);
            }
        }
        __syncthreads();
        #pragma unroll
        for (int i = 0; i < 4; i++) {
            int p = ty*4 + i;
            #pragma unroll
            for (int j = 0; j < 8; j++) {
                int f = tx + 16*j;
                sX[p*SXS + f] = acc[i][j] + sB2[f];
            }
        }
        __syncthreads();

        // ---- epilogue 1: per-output-element stats (256 elements) ----
        if (tid < 256) {
            int p = tid >> 1, side = tid & 1;
            const float* r = sX + p*SXS + side*64;
            float ss = 0.f, l0 = sLB[0], l1 = sLB[1];
            #pragma unroll 8
            for (int d = 0; d < 64; d++) {
                float v = r[d];
                ss = fmaf(v, v, ss);
                l0 = fmaf(v, sLW[2*d], l0);
                l1 = fmaf(v, sLW[2*d+1], l1);
            }
            float m = fmaxf(l0, l1);
            float x0 = expf(l0 - m), x1 = expf(l1 - m);
            float inv = 1.f / (x0 + x1);
            float p0 = x0 * inv, p1 = x1 * inv;
            int pp = pp0 + p;
            int n0 = 2*pp + side;
            int vv = side ? sVe[p] : sVx[p];
            float pt = vv ? p1 : p0;
            pt = fminf(fmaxf(pt, 1e-7f), 1.0f);
            out[LOFF + (b*11 + t)*Nn + n0] = -logf(pt);
            float* po = out + POFF + (((size_t)(b*Nn + n0))*11 + t)*2;
            po[0] = p0; po[1] = p1;
            out[NOFF + (b*11 + t)*Nn + n0] = sqrtf(ss);
            v_next[b*Nn + n0] = vv;
        }
        // ---- epilogue 2: coalesced e_next write (rows contiguous: n = 2*pp0 + row) ----
        float4* en = (float4*)(e_next + ((size_t)b*Nn + 2*pp0) * 64);
        for (int i = tid; i < 256*16; i += THREADS) {
            int row = i >> 4, q = i & 15;
            int p = row >> 1, side = row & 1;
            const float* r = sX + p*SXS + side*64 + q*4;
            en[i] = make_float4(r[0], r[1], r[2], r[3]);
        }
    }
}

// ---------------------------------------------------------------------------
extern "C" void kernel_launch(void* const* d_in, const int* in_sizes, int n_in,
                              void* d_out, int out_size)
{
    const int*   x     = (const int*)  d_in[0];
    const float* y     = (const float*)d_in[1];
    const float* embW  = (const float*)d_in[2];
    const float* embB  = (const float*)d_in[3];
    const float* lab   = (const float*)d_in[4];
    const float* cnW1  = (const float*)d_in[5];
    const float* cnb1  = (const float*)d_in[6];
    const float* cnW2  = (const float*)d_in[7];
    const float* cnb2  = (const float*)d_in[8];
    const float* bnW1  = (const float*)d_in[9];
    const float* bnb1  = (const float*)d_in[10];
    const float* bnW2  = (const float*)d_in[11];
    const float* bnb2  = (const float*)d_in[12];
    const float* llrW  = (const float*)d_in[13];
    const float* llrb  = (const float*)d_in[14];
    float* out = (float*)d_out;

    float *eA, *eB; int *vA, *vB;
    cudaGetSymbolAddress((void**)&eA, g_eA);
    cudaGetSymbolAddress((void**)&eB, g_eB);
    cudaGetSymbolAddress((void**)&vA, g_vA);
    cudaGetSymbolAddress((void**)&vB, g_vB);

    int smcount = 148;
    cudaDeviceGetAttribute(&smcount, cudaDevAttrMultiProcessorCount, 0);
    cudaFuncSetAttribute(iter_kernel, cudaFuncAttributeMaxDynamicSharedMemorySize, SMEM_BYTES);

    stage0_kernel<<<(Bb*Nn)/128, 128>>>(x, y, embW, embB, llrW, llrb, eA, out);

    for (int t = 1; t <= 10; t++) {
        const float* ec = (t & 1) ? eA : eB;
        float*       en = (t & 1) ? eB : eA;
        const int*   vc = (t == 1) ? x : ((t & 1) ? vB : vA);
        int*         vn = (t & 1) ? vA : vB;
        iter_kernel<<<smcount, THREADS, SMEM_BYTES>>>(
            ec, vc, en, vn,
            cnW1, cnb1, cnW2, cnb2,
            bnW1, bnb1, bnW2, bnb2,
            lab, llrW, llrb, out, t);
    }
}

// round 4
// speedup vs baseline: 2.4217x; 2.4217x over previous
#include <cuda_runtime.h>
#include <cuda_bf16.h>
#include <math.h>
#include <stdint.h>

#define Bb 256
#define Nn 1024
#define TILE_P 128
#define NTILES 1024
#define THREADS 512

// output buffer offsets (floats)
#define LOFF 0
#define POFF (Bb*11*Nn)
#define NOFF (POFF + Bb*Nn*11*2)

// smem byte offsets (bf16 tiles, row stride 136 elements = 272 B)
#define OXH  0
#define OXL  34816
#define OW1H 69632
#define OW1L 104448
#define OW2H 139264
#define OW2L 156672
#define OBIG 174080
// float/small region offsets (bytes from smem base)
#define OS_B1 (OBIG + 0)
#define OS_B2 (OBIG + 512)
#define OS_LW (OBIG + 1024)
#define OS_C  (OBIG + 1536)
#define OS_LB (OBIG + 2048)
#define OS_VX (OBIG + 2056)
#define OS_VE (OBIG + 2184)
#define SMEM_BYTES (OBIG + 2368)

__device__ float g_eA[Bb*Nn*64];
__device__ float g_eB[Bb*Nn*64];
__device__ int   g_vA[Bb*Nn];
__device__ int   g_vB[Bb*Nn];

// ---------------------------------------------------------------------------
__device__ __forceinline__ uint32_t su32(const void* p) {
    uint32_t a;
    asm("{ .reg .u64 t; cvta.to.shared.u64 t, %1; cvt.u32.u64 %0, t; }" : "=r"(a) : "l"(p));
    return a;
}
__device__ __forceinline__ void ldsm4(uint32_t* r, uint32_t addr) {
    asm volatile("ldmatrix.sync.aligned.m8n8.x4.shared.b16 {%0,%1,%2,%3}, [%4];"
        : "=r"(r[0]), "=r"(r[1]), "=r"(r[2]), "=r"(r[3]) : "r"(addr));
}
__device__ __forceinline__ void ldsm4t(uint32_t* r, uint32_t addr) {
    asm volatile("ldmatrix.sync.aligned.m8n8.x4.trans.shared.b16 {%0,%1,%2,%3}, [%4];"
        : "=r"(r[0]), "=r"(r[1]), "=r"(r[2]), "=r"(r[3]) : "r"(addr));
}
__device__ __forceinline__ void mma16816(float* c, const uint32_t* a, uint32_t b0, uint32_t b1) {
    asm volatile("mma.sync.aligned.m16n8k16.row.col.f32.bf16.bf16.f32 "
        "{%0,%1,%2,%3}, {%4,%5,%6,%7}, {%8,%9}, {%0,%1,%2,%3};"
        : "+f"(c[0]), "+f"(c[1]), "+f"(c[2]), "+f"(c[3])
        : "r"(a[0]), "r"(a[1]), "r"(a[2]), "r"(a[3]), "r"(b0), "r"(b1));
}
__device__ __forceinline__ void splitbf(float v, __nv_bfloat16& h, __nv_bfloat16& l) {
    h = __float2bfloat16_rn(v);
    l = __float2bfloat16_rn(v - __bfloat162float(h));
}
__device__ __forceinline__ uint32_t packbf(__nv_bfloat16 a, __nv_bfloat16 b) {
    __nv_bfloat162 t; t.x = a; t.y = b;
    return *(uint32_t*)&t;
}
__device__ __forceinline__ uint32_t packf(float a, float b) {
    __nv_bfloat162 t = __floats2bfloat162_rn(a, b);   // x=a (low), y=b
    return *(uint32_t*)&t;
}

// ---------------------------------------------------------------------------
// Stage 0 (unchanged from passing R1 kernel)
// ---------------------------------------------------------------------------
__global__ void stage0_kernel(const int* __restrict__ x, const float* __restrict__ y,
                              const float* __restrict__ embW, const float* __restrict__ embB,
                              const float* __restrict__ llrW, const float* __restrict__ llrb,
                              float* __restrict__ e0, float* __restrict__ out)
{
    __shared__ float sE[128*65];
    __shared__ float sWe[128], sBe[64], sLW[128], sLB[2];
    const int tid = threadIdx.x;
    if (tid < 128) sWe[tid] = embW[tid];
    if (tid < 64)  sBe[tid] = embB[tid];
    if (tid < 128) sLW[tid] = llrW[tid];
    if (tid < 2)   sLB[tid] = llrb[tid];
    __syncthreads();

    const int gi = blockIdx.x * 128 + tid;
    const int b  = gi >> 10;
    const int n0 = gi & 1023;
    const float y0 = y[2*gi], y1 = y[2*gi+1];

    float ss = 0.f, l0 = sLB[0], l1 = sLB[1];
    #pragma unroll 8
    for (int d = 0; d < 64; d++) {
        float e = fmaf(y0, sWe[d], fmaf(y1, sWe[64+d], sBe[d]));
        ss = fmaf(e, e, ss);
        l0 = fmaf(e, sLW[2*d], l0);
        l1 = fmaf(e, sLW[2*d+1], l1);
        sE[tid*65 + d] = e;
    }
    float m = fmaxf(l0, l1);
    float x0 = expf(l0 - m), x1 = expf(l1 - m);
    float inv = 1.f / (x0 + x1);
    float p0 = x0 * inv, p1 = x1 * inv;
    int vv = x[gi];
    float pt = vv ? p1 : p0;
    pt = fminf(fmaxf(pt, 1e-7f), 1.0f);
    out[LOFF + (b*11 + 0)*Nn + n0] = -logf(pt);
    float* po = out + POFF + (((size_t)(b*Nn + n0))*11 + 0)*2;
    po[0] = p0; po[1] = p1;
    out[NOFF + (b*11 + 0)*Nn + n0] = sqrtf(ss);
    __syncthreads();

    float4* dst = (float4*)(e0 + (size_t)blockIdx.x * 128 * 64);
    for (int i = tid; i < 128*16; i += 128) {
        int row = i >> 4, q = i & 15;
        const float* r = sE + row*65 + q*4;
        dst[i] = make_float4(r[0], r[1], r[2], r[3]);
    }
}

// ---------------------------------------------------------------------------
// Butterfly stage on the tensor pipe: mma.sync bf16 with 3-pass hi/lo split.
// GEMM1: C1[128x128] = X[128x128] @ W1cat ; GEMM2 (block-diag): per 64-col half.
// H stays in registers between GEMMs (C-frag == A-frag layout).
// ---------------------------------------------------------------------------
__global__ void __launch_bounds__(THREADS, 1)
iter_mma(const float* __restrict__ e_cur, const int* __restrict__ v_cur,
         float* __restrict__ e_next, int* __restrict__ v_next,
         const float* __restrict__ cnW1, const float* __restrict__ cnb1,
         const float* __restrict__ cnW2, const float* __restrict__ cnb2,
         const float* __restrict__ bnW1, const float* __restrict__ bnb1,
         const float* __restrict__ bnW2, const float* __restrict__ bnb2,
         const float* __restrict__ lab,  const float* __restrict__ llrW,
         const float* __restrict__ llrb, float* __restrict__ out, int t)
{
    extern __shared__ char sm[];
    const uint32_t sbase = su32(sm);
    __nv_bfloat16* sXh  = (__nv_bfloat16*)(sm + OXH);
    __nv_bfloat16* sXl  = (__nv_bfloat16*)(sm + OXL);
    __nv_bfloat16* sW1h = (__nv_bfloat16*)(sm + OW1H);
    __nv_bfloat16* sW1l = (__nv_bfloat16*)(sm + OW1L);
    __nv_bfloat16* sW2h = (__nv_bfloat16*)(sm + OW2H);
    __nv_bfloat16* sW2l = (__nv_bfloat16*)(sm + OW2L);
    float* sB1 = (float*)(sm + OS_B1);
    float* sB2 = (float*)(sm + OS_B2);
    float* sLW = (float*)(sm + OS_LW);
    float* sC  = (float*)(sm + OS_C);
    float* sLB = (float*)(sm + OS_LB);
    uint8_t* sVx = (uint8_t*)(sm + OS_VX);
    uint8_t* sVe = (uint8_t*)(sm + OS_VE);

    const int tid  = threadIdx.x;
    const int wid  = tid >> 5, lane = tid & 31;
    const int wr   = wid & 7,  wc   = wid >> 3;
    const int lq   = lane & 3, lg   = lane >> 2;
    const int l15  = lane & 15;
    const int lhi8 = (lane >> 4) << 3;

    // ---- stage weights -> smem (bf16 hi/lo) ----
    for (int i = tid; i < 128*128; i += THREADS) {
        int k = i >> 7, f = i & 127;
        float v = (f < 64) ? cnW1[k*64 + f] : bnW1[k*64 + (f - 64)];
        __nv_bfloat16 h, l; splitbf(v, h, l);
        sW1h[k*136 + f] = h; sW1l[k*136 + f] = l;
    }
    for (int i = tid; i < 64*128; i += THREADS) {
        int k = i >> 7, n = i & 127;
        float v = (n < 64) ? cnW2[k*64 + n] : bnW2[k*64 + (n - 64)];
        __nv_bfloat16 h, l; splitbf(v, h, l);
        sW2h[k*136 + n] = h; sW2l[k*136 + n] = l;
    }
    if (tid < 128) {
        sB1[tid] = (tid < 64) ? cnb1[tid] : bnb1[tid - 64];
        sB2[tid] = (tid < 64) ? cnb2[tid] : bnb2[tid - 64];
        sLW[tid] = llrW[tid];
    }
    if (tid < 2) sLB[tid] = llrb[tid];
    if (tid < 128) {
        int j = tid >> 6, f = tid & 63;
        float s = 0.f;
        for (int k = 0; k < 64; k++) s = fmaf(lab[j*64 + k], bnW1[(128 + k)*64 + f], s);
        sC[tid] = s;
    }

    const int hs    = 1 << (t - 1);
    const int shl   = t - 1;
    const int jmask = hs - 1;

    // per-lane ldmatrix address bases (byte offsets into smem)
    const uint32_t aA  = sbase + OXH  + (uint32_t)(((16*wr + l15)*136 + lhi8) * 2);
    const uint32_t aB1 = sbase + OW1H + (uint32_t)((l15*136 + 64*wc + lhi8) * 2);
    const uint32_t aB2 = sbase + OW2H + (uint32_t)((l15*136 + 64*wc + lhi8) * 2);
    const int mlo = 16*wr + lg, mhi = mlo + 8;

    for (int tile = blockIdx.x; tile < NTILES; tile += gridDim.x) {
        const int pg0 = tile * TILE_P;
        const int b   = pg0 >> 9;
        const int pp0 = pg0 & 511;
        __syncthreads();                       // previous-iter smem reads done

        // ---- gather X tile (hi/lo bf16) ----
        const float* eb = e_cur + (size_t)b * (Nn*64);
        for (int i = tid; i < 128*32; i += THREADS) {
            int r = i >> 5, c4 = i & 31;
            int pp = pp0 + r;
            int oddn = ((pp >> shl) << t) + (pp & jmask);
            int n = oddn + ((c4 >= 16) ? hs : 0);
            float4 v4 = *(const float4*)(eb + (size_t)n*64 + (c4 & 15)*4);
            int cc = c4 * 4;
            __nv_bfloat16 hx,lx,hy,ly,hz,lz,hw,lw;
            splitbf(v4.x,hx,lx); splitbf(v4.y,hy,ly);
            splitbf(v4.z,hz,lz); splitbf(v4.w,hw,lw);
            uint32_t* dh = (uint32_t*)&sXh[r*136 + cc];
            uint32_t* dl = (uint32_t*)&sXl[r*136 + cc];
            dh[0] = packbf(hx,hy); dh[1] = packbf(hz,hw);
            dl[0] = packbf(lx,ly); dl[1] = packbf(lz,lw);
        }
        if (tid < 128) {
            int pp = pp0 + tid;
            int oddn = ((pp >> shl) << t) + (pp & jmask);
            int vo = v_cur[b*Nn + oddn];
            int ve = v_cur[b*Nn + oddn + hs];
            sVx[tid] = (uint8_t)((vo + ve) & 1);
            sVe[tid] = (uint8_t)ve;
        }
        __syncthreads();

        // ---- GEMM1: acc1 = X @ W1cat (3-pass bf16) ----
        float acc1[8][4];
        #pragma unroll
        for (int i = 0; i < 8; i++)
            #pragma unroll
            for (int j = 0; j < 4; j++) acc1[i][j] = 0.f;

        #pragma unroll
        for (int kt = 0; kt < 8; kt++) {
            uint32_t ah[4], al[4];
            ldsm4(ah, aA + 32*kt);
            ldsm4(al, aA + (OXL - OXH) + 32*kt);
            #pragma unroll
            for (int ntp = 0; ntp < 4; ntp++) {
                uint32_t bh[4], bl[4];
                uint32_t ba = aB1 + kt*4352 + ntp*32;
                ldsm4t(bh, ba);
                ldsm4t(bl, ba + (OW1L - OW1H));
                mma16816(acc1[2*ntp],   ah, bh[0], bh[1]);
                mma16816(acc1[2*ntp],   al, bh[0], bh[1]);
                mma16816(acc1[2*ntp],   ah, bl[0], bl[1]);
                mma16816(acc1[2*ntp+1], ah, bh[2], bh[3]);
                mma16816(acc1[2*ntp+1], al, bh[2], bh[3]);
                mma16816(acc1[2*ntp+1], ah, bl[2], bl[3]);
            }
        }

        // ---- H epilogue in registers: bias + c_vx + relu, split+pack ----
        const int vxlo = sVx[mlo], vxhi = sVx[mhi];
        uint32_t pH0h[8], pH1h[8], pH0l[8], pH1l[8];
        #pragma unroll
        for (int nt = 0; nt < 8; nt++) {
            int d0 = 8*nt + 2*lq;
            int f0 = 64*wc + d0;
            float h00 = acc1[nt][0] + sB1[f0];
            float h01 = acc1[nt][1] + sB1[f0+1];
            float h10 = acc1[nt][2] + sB1[f0];
            float h11 = acc1[nt][3] + sB1[f0+1];
            if (wc) {
                h00 += sC[vxlo*64 + d0];  h01 += sC[vxlo*64 + d0 + 1];
                h10 += sC[vxhi*64 + d0];  h11 += sC[vxhi*64 + d0 + 1];
            }
            h00 = fmaxf(h00, 0.f); h01 = fmaxf(h01, 0.f);
            h10 = fmaxf(h10, 0.f); h11 = fmaxf(h11, 0.f);
            __nv_bfloat16 a,b1_,c,d,e,f,g,h;
            splitbf(h00,a,b1_); splitbf(h01,c,d);
            splitbf(h10,e,f);   splitbf(h11,g,h);
            pH0h[nt] = packbf(a,c); pH0l[nt] = packbf(b1_,d);
            pH1h[nt] = packbf(e,g); pH1l[nt] = packbf(f,h);
        }

        // ---- GEMM2: acc2 = H @ W2block (3-pass bf16), A from registers ----
        float acc2[8][4];
        #pragma unroll
        for (int i = 0; i < 8; i++)
            #pragma unroll
            for (int j = 0; j < 4; j++) acc2[i][j] = 0.f;

        #pragma unroll
        for (int kt = 0; kt < 4; kt++) {
            uint32_t a2h[4] = {pH0h[2*kt], pH1h[2*kt], pH0h[2*kt+1], pH1h[2*kt+1]};
            uint32_t a2l[4] = {pH0l[2*kt], pH1l[2*kt], pH0l[2*kt+1], pH1l[2*kt+1]};
            #pragma unroll
            for (int ntp = 0; ntp < 4; ntp++) {
                uint32_t bh[4], bl[4];
                uint32_t ba = aB2 + kt*4352 + ntp*32;
                ldsm4t(bh, ba);
                ldsm4t(bl, ba + (OW2L - OW2H));
                mma16816(acc2[2*ntp],   a2h, bh[0], bh[1]);
                mma16816(acc2[2*ntp],   a2l, bh[0], bh[1]);
                mma16816(acc2[2*ntp],   a2h, bl[0], bl[1]);
                mma16816(acc2[2*ntp+1], a2h, bh[2], bh[3]);
                mma16816(acc2[2*ntp+1], a2l, bh[2], bh[3]);
                mma16816(acc2[2*ntp+1], a2h, bl[2], bl[3]);
            }
        }

        // ---- output epilogue: bias, stats, global writes ----
        float pssL = 0.f, pl0L = 0.f, pl1L = 0.f;
        float pssH = 0.f, pl0H = 0.f, pl1H = 0.f;
        #pragma unroll
        for (int nt = 0; nt < 8; nt++) {
            int d0 = 8*nt + 2*lq;
            int f0 = 64*wc + d0;
            float e00 = acc2[nt][0] + sB2[f0];
            float e01 = acc2[nt][1] + sB2[f0+1];
            float e10 = acc2[nt][2] + sB2[f0];
            float e11 = acc2[nt][3] + sB2[f0+1];
            acc2[nt][0] = e00; acc2[nt][1] = e01;
            acc2[nt][2] = e10; acc2[nt][3] = e11;
            pssL = fmaf(e00,e00, fmaf(e01,e01, pssL));
            pssH = fmaf(e10,e10, fmaf(e11,e11, pssH));
            pl0L = fmaf(e00, sLW[2*d0],   fmaf(e01, sLW[2*d0+2], pl0L));
            pl1L = fmaf(e00, sLW[2*d0+1], fmaf(e01, sLW[2*d0+3], pl1L));
            pl0H = fmaf(e10, sLW[2*d0],   fmaf(e11, sLW[2*d0+2], pl0H));
            pl1H = fmaf(e10, sLW[2*d0+1], fmaf(e11, sLW[2*d0+3], pl1H));
        }
        #pragma unroll
        for (int off = 1; off <= 2; off <<= 1) {
            pssL += __shfl_xor_sync(0xffffffffu, pssL, off);
            pl0L += __shfl_xor_sync(0xffffffffu, pl0L, off);
            pl1L += __shfl_xor_sync(0xffffffffu, pl1L, off);
            pssH += __shfl_xor_sync(0xffffffffu, pssH, off);
            pl0H += __shfl_xor_sync(0xffffffffu, pl0H, off);
            pl1H += __shfl_xor_sync(0xffffffffu, pl1H, off);
        }
        if (lq == 0) {
            #pragma unroll
            for (int half = 0; half < 2; half++) {
                int p   = half ? mhi : mlo;
                float ss = half ? pssH : pssL;
                float l0 = (half ? pl0H : pl0L) + sLB[0];
                float l1 = (half ? pl1H : pl1L) + sLB[1];
                float m = fmaxf(l0, l1);
                float x0 = expf(l0 - m), x1 = expf(l1 - m);
                float inv = 1.f / (x0 + x1);
                float p0 = x0 * inv, p1 = x1 * inv;
                int vv = wc ? (int)sVe[p] : (int)sVx[p];
                float pt = vv ? p1 : p0;
                pt = fminf(fmaxf(pt, 1e-7f), 1.0f);
                int n = 2*(pp0 + p) + wc;
                out[LOFF + (b*11 + t)*Nn + n] = -logf(pt);
                float* po = out + POFF + (((size_t)(b*Nn + n))*11 + t)*2;
                po[0] = p0; po[1] = p1;
                out[NOFF + (b*11 + t)*Nn + n] = sqrtf(ss);
                v_next[b*Nn + n] = vv;
            }
        }
        {
            float* rl = e_next + ((size_t)b*Nn + 2*(pp0 + mlo) + wc)*64;
            float* rh = e_next + ((size_t)b*Nn + 2*(pp0 + mhi) + wc)*64;
            #pragma unroll
            for (int nt = 0; nt < 8; nt++) {
                int d0 = 8*nt + 2*lq;
                *(float2*)(rl + d0) = make_float2(acc2[nt][0], acc2[nt][1]);
                *(float2*)(rh + d0) = make_float2(acc2[nt][2], acc2[nt][3]);
            }
        }
    }
}

// ---------------------------------------------------------------------------
extern "C" void kernel_launch(void* const* d_in, const int* in_sizes, int n_in,
                              void* d_out, int out_size)
{
    const int*   x     = (const int*)  d_in[0];
    const float* y     = (const float*)d_in[1];
    const float* embW  = (const float*)d_in[2];
    const float* embB  = (const float*)d_in[3];
    const float* lab   = (const float*)d_in[4];
    const float* cnW1  = (const float*)d_in[5];
    const float* cnb1  = (const float*)d_in[6];
    const float* cnW2  = (const float*)d_in[7];
    const float* cnb2  = (const float*)d_in[8];
    const float* bnW1  = (const float*)d_in[9];
    const float* bnb1  = (const float*)d_in[10];
    const float* bnW2  = (const float*)d_in[11];
    const float* bnb2  = (const float*)d_in[12];
    const float* llrW  = (const float*)d_in[13];
    const float* llrb  = (const float*)d_in[14];
    float* out = (float*)d_out;

    float *eA, *eB; int *vA, *vB;
    cudaGetSymbolAddress((void**)&eA, g_eA);
    cudaGetSymbolAddress((void**)&eB, g_eB);
    cudaGetSymbolAddress((void**)&vA, g_vA);
    cudaGetSymbolAddress((void**)&vB, g_vB);

    int smcount = 148;
    cudaDeviceGetAttribute(&smcount, cudaDevAttrMultiProcessorCount, 0);
    cudaFuncSetAttribute(iter_mma, cudaFuncAttributeMaxDynamicSharedMemorySize, SMEM_BYTES);

    stage0_kernel<<<(Bb*Nn)/128, 128>>>(x, y, embW, embB, llrW, llrb, eA, out);

    for (int t = 1; t <= 10; t++) {
        const float* ec = (t & 1) ? eA : eB;
        float*       en = (t & 1) ? eB : eA;
        const int*   vc = (t == 1) ? x : ((t & 1) ? vB : vA);
        int*         vn = (t & 1) ? vA : vB;
        iter_mma<<<smcount, THREADS, SMEM_BYTES>>>(
            ec, vc, en, vn,
            cnW1, cnb1, cnW2, cnb2,
            bnW1, bnb1, bnW2, bnb2,
            lab, llrW, llrb, out, t);
    }
}

// round 6
// speedup vs baseline: 2.4534x; 1.0131x over previous
#include <cuda_runtime.h>
#include <cuda_bf16.h>
#include <math.h>
#include <stdint.h>

#define Bb 256
#define Nn 1024
#define TILE_P 128
#define NTILES 1024
#define THREADS 512

// output buffer offsets (floats)
#define LOFF 0
#define POFF (Bb*11*Nn)
#define NOFF (POFF + Bb*Nn*11*2)

// smem byte offsets. X: 2 bufs x (hi,lo) x 128 rows x 256B (swizzled chunks)
#define OX0  0
#define OW1H 131072
#define OW1L 163840
#define OW2H 196608
#define OW2L 212992
#define OBIG 229376
#define OS_B1 (OBIG + 0)
#define OS_B2 (OBIG + 512)
#define OS_LW (OBIG + 1024)
#define OS_C  (OBIG + 1536)
#define OS_LB (OBIG + 2048)
#define OS_VX (OBIG + 2056)
#define OS_VE (OBIG + 2312)
#define SMEM_BYTES (OBIG + 2568)

__device__ __align__(256) __nv_bfloat16 g_eHA[Bb*Nn*64];
__device__ __align__(256) __nv_bfloat16 g_eLA[Bb*Nn*64];
__device__ __align__(256) __nv_bfloat16 g_eHB[Bb*Nn*64];
__device__ __align__(256) __nv_bfloat16 g_eLB[Bb*Nn*64];
__device__ int g_vA[Bb*Nn];
__device__ int g_vB[Bb*Nn];

// ---------------------------------------------------------------------------
__device__ __forceinline__ uint32_t su32(const void* p) {
    uint32_t a;
    asm("{ .reg .u64 t; cvta.to.shared.u64 t, %1; cvt.u32.u64 %0, t; }" : "=r"(a) : "l"(p));
    return a;
}
__device__ __forceinline__ void ldsm4(uint32_t* r, uint32_t addr) {
    asm volatile("ldmatrix.sync.aligned.m8n8.x4.shared.b16 {%0,%1,%2,%3}, [%4];"
        : "=r"(r[0]), "=r"(r[1]), "=r"(r[2]), "=r"(r[3]) : "r"(addr));
}
__device__ __forceinline__ void ldsm4t(uint32_t* r, uint32_t addr) {
    asm volatile("ldmatrix.sync.aligned.m8n8.x4.trans.shared.b16 {%0,%1,%2,%3}, [%4];"
        : "=r"(r[0]), "=r"(r[1]), "=r"(r[2]), "=r"(r[3]) : "r"(addr));
}
__device__ __forceinline__ void mma16816(float* c, const uint32_t* a, uint32_t b0, uint32_t b1) {
    asm volatile("mma.sync.aligned.m16n8k16.row.col.f32.bf16.bf16.f32 "
        "{%0,%1,%2,%3}, {%4,%5,%6,%7}, {%8,%9}, {%0,%1,%2,%3};"
        : "+f"(c[0]), "+f"(c[1]), "+f"(c[2]), "+f"(c[3])
        : "r"(a[0]), "r"(a[1]), "r"(a[2]), "r"(a[3]), "r"(b0), "r"(b1));
}
__device__ __forceinline__ void splitbf(float v, __nv_bfloat16& h, __nv_bfloat16& l) {
    h = __float2bfloat16_rn(v);
    l = __float2bfloat16_rn(v - __bfloat162float(h));
}
__device__ __forceinline__ uint32_t packbf(__nv_bfloat16 a, __nv_bfloat16 b) {
    __nv_bfloat162 t; t.x = a; t.y = b;
    return *(uint32_t*)&t;
}
__device__ __forceinline__ void cpa16(uint32_t dst, const void* src) {
    asm volatile("cp.async.cg.shared.global [%0], [%1], 16;" :: "r"(dst), "l"(src));
}
// swizzled byte offset of 16B chunk c16 in row r (256B rows)
__device__ __forceinline__ uint32_t swz(int r, int c16) {
    return (uint32_t)((r << 8) + (((c16 & 8) | ((c16 ^ r) & 7)) << 4));
}

// ---------------------------------------------------------------------------
// Stage 0
// ---------------------------------------------------------------------------
__global__ void stage0_kernel(const int* __restrict__ x, const float* __restrict__ y,
                              const float* __restrict__ embW, const float* __restrict__ embB,
                              const float* __restrict__ llrW, const float* __restrict__ llrb,
                              __nv_bfloat16* __restrict__ eH, __nv_bfloat16* __restrict__ eL,
                              float* __restrict__ out)
{
    __shared__ float sE[128*65];
    __shared__ float sWe[128], sBe[64], sLW[128], sLB[2];
    const int tid = threadIdx.x;
    if (tid < 128) sWe[tid] = embW[tid];
    if (tid < 64)  sBe[tid] = embB[tid];
    if (tid < 128) sLW[tid] = llrW[tid];
    if (tid < 2)   sLB[tid] = llrb[tid];
    __syncthreads();

    const int gi = blockIdx.x * 128 + tid;
    const int b  = gi >> 10;
    const int n0 = gi & 1023;
    const float y0 = y[2*gi], y1 = y[2*gi+1];

    float ss = 0.f, l0 = sLB[0], l1 = sLB[1];
    #pragma unroll 8
    for (int d = 0; d < 64; d++) {
        float e = fmaf(y0, sWe[d], fmaf(y1, sWe[64+d], sBe[d]));
        ss = fmaf(e, e, ss);
        l0 = fmaf(e, sLW[2*d], l0);
        l1 = fmaf(e, sLW[2*d+1], l1);
        sE[tid*65 + d] = e;
    }
    float m = fmaxf(l0, l1);
    float x0 = expf(l0 - m), x1 = expf(l1 - m);
    float inv = 1.f / (x0 + x1);
    float p0 = x0 * inv, p1 = x1 * inv;
    int vv = x[gi];
    float pt = vv ? p1 : p0;
    pt = fminf(fmaxf(pt, 1e-7f), 1.0f);
    out[LOFF + (b*11 + 0)*Nn + n0] = -logf(pt);
    float* po = out + POFF + (((size_t)(b*Nn + n0))*11 + 0)*2;
    po[0] = p0; po[1] = p1;
    out[NOFF + (b*11 + 0)*Nn + n0] = sqrtf(ss);
    __syncthreads();

    uint32_t* dH = (uint32_t*)(eH + (size_t)blockIdx.x * 128 * 64);
    uint32_t* dL = (uint32_t*)(eL + (size_t)blockIdx.x * 128 * 64);
    for (int i = tid; i < 128*32; i += 128) {
        int row = i >> 5, q = i & 31;
        float a = sE[row*65 + 2*q], c = sE[row*65 + 2*q + 1];
        __nv_bfloat16 ha, la, hc, lc;
        splitbf(a, ha, la); splitbf(c, hc, lc);
        dH[i] = packbf(ha, hc);
        dL[i] = packbf(la, lc);
    }
}

// ---------------------------------------------------------------------------
// Butterfly stage: cp.async double-buffered gather + bf16 3-pass mma.sync
// ---------------------------------------------------------------------------
__global__ void __launch_bounds__(THREADS, 1)
iter_mma(const __nv_bfloat16* __restrict__ eHc, const __nv_bfloat16* __restrict__ eLc,
         const int* __restrict__ v_cur,
         __nv_bfloat16* __restrict__ eHn, __nv_bfloat16* __restrict__ eLn,
         int* __restrict__ v_next,
         const float* __restrict__ cnW1, const float* __restrict__ cnb1,
         const float* __restrict__ cnW2, const float* __restrict__ cnb2,
         const float* __restrict__ bnW1, const float* __restrict__ bnb1,
         const float* __restrict__ bnW2, const float* __restrict__ bnb2,
         const float* __restrict__ lab,  const float* __restrict__ llrW,
         const float* __restrict__ llrb, float* __restrict__ out, int t)
{
    extern __shared__ char sm[];
    const uint32_t sbase = su32(sm);
    float* sB1 = (float*)(sm + OS_B1);
    float* sB2 = (float*)(sm + OS_B2);
    float* sLW = (float*)(sm + OS_LW);
    float* sC  = (float*)(sm + OS_C);
    float* sLB = (float*)(sm + OS_LB);
    uint8_t* sVx = (uint8_t*)(sm + OS_VX);
    uint8_t* sVe = (uint8_t*)(sm + OS_VE);

    const int tid  = threadIdx.x;
    const int wid  = tid >> 5, lane = tid & 31;
    const int wr   = wid & 7,  wc   = wid >> 3;
    const int lq   = lane & 3, lg   = lane >> 2;
    const int l15  = lane & 15;
    const int hi8  = lane >> 4;
    const int rx   = l15 & 7;

    // ---- stage weights -> smem (bf16 hi/lo, swizzled 256B rows) ----
    for (int i = tid; i < 128*128; i += THREADS) {
        int k = i >> 7, f = i & 127;
        float v = (f < 64) ? cnW1[k*64 + f] : bnW1[k*64 + (f - 64)];
        __nv_bfloat16 h, l; splitbf(v, h, l);
        uint32_t o = swz(k, f >> 3) + (f & 7)*2;
        *(__nv_bfloat16*)(sm + OW1H + o) = h;
        *(__nv_bfloat16*)(sm + OW1L + o) = l;
    }
    for (int i = tid; i < 64*128; i += THREADS) {
        int k = i >> 7, n = i & 127;
        float v = (n < 64) ? cnW2[k*64 + n] : bnW2[k*64 + (n - 64)];
        __nv_bfloat16 h, l; splitbf(v, h, l);
        uint32_t o = swz(k, n >> 3) + (n & 7)*2;
        *(__nv_bfloat16*)(sm + OW2H + o) = h;
        *(__nv_bfloat16*)(sm + OW2L + o) = l;
    }
    if (tid < 128) {
        sB1[tid] = (tid < 64) ? cnb1[tid] : bnb1[tid - 64];
        sB2[tid] = (tid < 64) ? cnb2[tid] : bnb2[tid - 64];
        sLW[tid] = llrW[tid];
    }
    if (tid < 2) sLB[tid] = llrb[tid];
    if (tid < 128) {
        int j = tid >> 6, f = tid & 63;
        float s = 0.f;
        for (int k = 0; k < 64; k++) s = fmaf(lab[j*64 + k], bnW1[(128 + k)*64 + f], s);
        sC[tid] = s;
    }

    const int hs    = 1 << (t - 1);
    const int shl   = t - 1;
    const int jmask = hs - 1;
    const int mlo = 16*wr + lg, mhi = mlo + 8;
    const uint32_t aArow = (uint32_t)((16*wr + l15) << 8);
    uint32_t bswz[4];
    #pragma unroll
    for (int ntp = 0; ntp < 4; ntp++) {
        int cb = 8*wc + 2*ntp + hi8;
        bswz[ntp] = (uint32_t)((((cb & 8) | ((cb ^ rx) & 7))) << 4);
    }

    // ---- tile issue: cp.async gather of X (hi/lo) + v loads ----
    auto issue = [&](int tile, int buf) {
        if (tile < NTILES) {
            const int pg0 = tile * TILE_P;
            const int b   = pg0 >> 9;
            const int pp0 = pg0 & 511;
            const __nv_bfloat16* ehb = eHc + (size_t)b * (Nn*64);
            const __nv_bfloat16* elb = eLc + (size_t)b * (Nn*64);
            const uint32_t xh = sbase + buf*65536;
            #pragma unroll
            for (int ii = 0; ii < 4; ii++) {
                int i = tid + ii*THREADS;          // 2048 chunks
                int r = i >> 4, c16 = i & 15;
                int pp = pp0 + r;
                int oddn = ((pp >> shl) << t) + (pp & jmask);
                int n = oddn + ((c16 >> 3) ? hs : 0);
                uint32_t doff = swz(r, c16);
                size_t soff = (size_t)n*128 + (c16 & 7)*16;
                cpa16(xh + doff,         (const char*)ehb + soff);
                cpa16(xh + 32768 + doff, (const char*)elb + soff);
            }
            if (tid < 128) {
                int pp = pp0 + tid;
                int oddn = ((pp >> shl) << t) + (pp & jmask);
                int vo = v_cur[b*Nn + oddn];
                int ve = v_cur[b*Nn + oddn + hs];
                sVx[buf*128 + tid] = (uint8_t)((vo + ve) & 1);
                sVe[buf*128 + tid] = (uint8_t)ve;
            }
        }
        asm volatile("cp.async.commit_group;" ::: "memory");
    };

    int buf = 0;
    __syncthreads();                    // weights + sC ready before first compute
    issue((int)blockIdx.x, 0);

    for (int tile = blockIdx.x; tile < NTILES; tile += gridDim.x) {
        issue(tile + (int)gridDim.x, buf ^ 1);
        asm volatile("cp.async.wait_group 1;" ::: "memory");
        __syncthreads();

        const int pg0 = tile * TILE_P;
        const int b   = pg0 >> 9;
        const int pp0 = pg0 & 511;
        const uint32_t xbase = sbase + buf*65536;

        // ---- GEMM1: acc1 = X @ W1cat (3-pass bf16) ----
        float acc1[8][4];
        #pragma unroll
        for (int i = 0; i < 8; i++)
            #pragma unroll
            for (int j = 0; j < 4; j++) acc1[i][j] = 0.f;

        #pragma unroll
        for (int kt = 0; kt < 8; kt++) {
            int ch = 2*kt + hi8;
            uint32_t axh = xbase + aArow + ((((ch & 8) | ((ch ^ rx) & 7))) << 4);
            uint32_t ah[4], al[4];
            ldsm4(ah, axh);
            ldsm4(al, axh + 32768);
            uint32_t brow = sbase + OW1H + (uint32_t)((16*kt + l15) << 8);
            #pragma unroll
            for (int ntp = 0; ntp < 4; ntp++) {
                uint32_t bh[4], bl[4];
                uint32_t ba = brow + bswz[ntp];
                ldsm4t(bh, ba);
                ldsm4t(bl, ba + (OW1L - OW1H));
                mma16816(acc1[2*ntp],   ah, bh[0], bh[1]);
                mma16816(acc1[2*ntp],   al, bh[0], bh[1]);
                mma16816(acc1[2*ntp],   ah, bl[0], bl[1]);
                mma16816(acc1[2*ntp+1], ah, bh[2], bh[3]);
                mma16816(acc1[2*ntp+1], al, bh[2], bh[3]);
                mma16816(acc1[2*ntp+1], ah, bl[2], bl[3]);
            }
        }

        // ---- H epilogue in registers ----
        const int vxlo = sVx[buf*128 + mlo], vxhi = sVx[buf*128 + mhi];
        uint32_t pH0h[8], pH1h[8], pH0l[8], pH1l[8];
        #pragma unroll
        for (int nt = 0; nt < 8; nt++) {
            int d0 = 8*nt + 2*lq;
            int f0 = 64*wc + d0;
            float h00 = acc1[nt][0] + sB1[f0];
            float h01 = acc1[nt][1] + sB1[f0+1];
            float h10 = acc1[nt][2] + sB1[f0];
            float h11 = acc1[nt][3] + sB1[f0+1];
            if (wc) {
                h00 += sC[vxlo*64 + d0];  h01 += sC[vxlo*64 + d0 + 1];
                h10 += sC[vxhi*64 + d0];  h11 += sC[vxhi*64 + d0 + 1];
            }
            h00 = fmaxf(h00, 0.f); h01 = fmaxf(h01, 0.f);
            h10 = fmaxf(h10, 0.f); h11 = fmaxf(h11, 0.f);
            __nv_bfloat16 a,b1_,c,d,e,f,g,h;
            splitbf(h00,a,b1_); splitbf(h01,c,d);
            splitbf(h10,e,f);   splitbf(h11,g,h);
            pH0h[nt] = packbf(a,c); pH0l[nt] = packbf(b1_,d);
            pH1h[nt] = packbf(e,g); pH1l[nt] = packbf(f,h);
        }

        // ---- GEMM2 ----
        float acc2[8][4];
        #pragma unroll
        for (int i = 0; i < 8; i++)
            #pragma unroll
            for (int j = 0; j < 4; j++) acc2[i][j] = 0.f;

        #pragma unroll
        for (int kt = 0; kt < 4; kt++) {
            uint32_t a2h[4] = {pH0h[2*kt], pH1h[2*kt], pH0h[2*kt+1], pH1h[2*kt+1]};
            uint32_t a2l[4] = {pH0l[2*kt], pH1l[2*kt], pH0l[2*kt+1], pH1l[2*kt+1]};
            uint32_t brow = sbase + OW2H + (uint32_t)((16*kt + l15) << 8);
            #pragma unroll
            for (int ntp = 0; ntp < 4; ntp++) {
                uint32_t bh[4], bl[4];
                uint32_t ba = brow + bswz[ntp];
                ldsm4t(bh, ba);
                ldsm4t(bl, ba + (OW2L - OW2H));
                mma16816(acc2[2*ntp],   a2h, bh[0], bh[1]);
                mma16816(acc2[2*ntp],   a2l, bh[0], bh[1]);
                mma16816(acc2[2*ntp],   a2h, bl[0], bl[1]);
                mma16816(acc2[2*ntp+1], a2h, bh[2], bh[3]);
                mma16816(acc2[2*ntp+1], a2l, bh[2], bh[3]);
                mma16816(acc2[2*ntp+1], a2h, bl[2], bl[3]);
            }
        }

        // ---- output epilogue ----
        float pssL = 0.f, pl0L = 0.f, pl1L = 0.f;
        float pssH = 0.f, pl0H = 0.f, pl1H = 0.f;
        #pragma unroll
        for (int nt = 0; nt < 8; nt++) {
            int d0 = 8*nt + 2*lq;
            int f0 = 64*wc + d0;
            float e00 = acc2[nt][0] + sB2[f0];
            float e01 = acc2[nt][1] + sB2[f0+1];
            float e10 = acc2[nt][2] + sB2[f0];
            float e11 = acc2[nt][3] + sB2[f0+1];
            acc2[nt][0] = e00; acc2[nt][1] = e01;
            acc2[nt][2] = e10; acc2[nt][3] = e11;
            pssL = fmaf(e00,e00, fmaf(e01,e01, pssL));
            pssH = fmaf(e10,e10, fmaf(e11,e11, pssH));
            pl0L = fmaf(e00, sLW[2*d0],   fmaf(e01, sLW[2*d0+2], pl0L));
            pl1L = fmaf(e00, sLW[2*d0+1], fmaf(e01, sLW[2*d0+3], pl1L));
            pl0H = fmaf(e10, sLW[2*d0],   fmaf(e11, sLW[2*d0+2], pl0H));
            pl1H = fmaf(e10, sLW[2*d0+1], fmaf(e11, sLW[2*d0+3], pl1H));
        }
        #pragma unroll
        for (int off = 1; off <= 2; off <<= 1) {
            pssL += __shfl_xor_sync(0xffffffffu, pssL, off);
            pl0L += __shfl_xor_sync(0xffffffffu, pl0L, off);
            pl1L += __shfl_xor_sync(0xffffffffu, pl1L, off);
            pssH += __shfl_xor_sync(0xffffffffu, pssH, off);
            pl0H += __shfl_xor_sync(0xffffffffu, pl0H, off);
            pl1H += __shfl_xor_sync(0xffffffffu, pl1H, off);
        }
        if (lq == 0) {
            #pragma unroll
            for (int half = 0; half < 2; half++) {
                int p   = half ? mhi : mlo;
                float ss = half ? pssH : pssL;
                float l0 = (half ? pl0H : pl0L) + sLB[0];
                float l1 = (half ? pl1H : pl1L) + sLB[1];
                float m = fmaxf(l0, l1);
                float x0 = expf(l0 - m), x1 = expf(l1 - m);
                float inv = 1.f / (x0 + x1);
                float p0 = x0 * inv, p1 = x1 * inv;
                int vv = wc ? (int)sVe[buf*128 + p] : (int)sVx[buf*128 + p];
                float pt = vv ? p1 : p0;
                pt = fminf(fmaxf(pt, 1e-7f), 1.0f);
                int n = 2*(pp0 + p) + wc;
                out[LOFF + (b*11 + t)*Nn + n] = -logf(pt);
                float* po = out + POFF + (((size_t)(b*Nn + n))*11 + t)*2;
                po[0] = p0; po[1] = p1;
                out[NOFF + (b*11 + t)*Nn + n] = sqrtf(ss);
                v_next[b*Nn + n] = vv;
            }
        }
        {
            size_t rlo = ((size_t)b*Nn + 2*(pp0 + mlo) + wc)*64;
            size_t rhi = ((size_t)b*Nn + 2*(pp0 + mhi) + wc)*64;
            #pragma unroll
            for (int nt = 0; nt < 8; nt++) {
                int d0 = 8*nt + 2*lq;
                __nv_bfloat16 h0,l0,h1,l1,h2,l2,h3,l3;
                splitbf(acc2[nt][0], h0, l0); splitbf(acc2[nt][1], h1, l1);
                splitbf(acc2[nt][2], h2, l2); splitbf(acc2[nt][3], h3, l3);
                *(uint32_t*)(eHn + rlo + d0) = packbf(h0, h1);
                *(uint32_t*)(eLn + rlo + d0) = packbf(l0, l1);
                *(uint32_t*)(eHn + rhi + d0) = packbf(h2, h3);
                *(uint32_t*)(eLn + rhi + d0) = packbf(l2, l3);
            }
        }
        __syncthreads();
        buf ^= 1;
    }
}

// ---------------------------------------------------------------------------
extern "C" void kernel_launch(void* const* d_in, const int* in_sizes, int n_in,
                              void* d_out, int out_size)
{
    const int*   x     = (const int*)  d_in[0];
    const float* y     = (const float*)d_in[1];
    const float* embW  = (const float*)d_in[2];
    const float* embB  = (const float*)d_in[3];
    const float* lab   = (const float*)d_in[4];
    const float* cnW1  = (const float*)d_in[5];
    const float* cnb1  = (const float*)d_in[6];
    const float* cnW2  = (const float*)d_in[7];
    const float* cnb2  = (const float*)d_in[8];
    const float* bnW1  = (const float*)d_in[9];
    const float* bnb1  = (const float*)d_in[10];
    const float* bnW2  = (const float*)d_in[11];
    const float* bnb2  = (const float*)d_in[12];
    const float* llrW  = (const float*)d_in[13];
    const float* llrb  = (const float*)d_in[14];
    float* out = (float*)d_out;

    __nv_bfloat16 *eHA, *eLA, *eHB, *eLB; int *vA, *vB;
    cudaGetSymbolAddress((void**)&eHA, g_eHA);
    cudaGetSymbolAddress((void**)&eLA, g_eLA);
    cudaGetSymbolAddress((void**)&eHB, g_eHB);
    cudaGetSymbolAddress((void**)&eLB, g_eLB);
    cudaGetSymbolAddress((void**)&vA, g_vA);
    cudaGetSymbolAddress((void**)&vB, g_vB);

    int smcount = 148;
    cudaDeviceGetAttribute(&smcount, cudaDevAttrMultiProcessorCount, 0);
    cudaFuncSetAttribute(iter_mma, cudaFuncAttributeMaxDynamicSharedMemorySize, SMEM_BYTES);

    stage0_kernel<<<(Bb*Nn)/128, 128>>>(x, y, embW, embB, llrW, llrb, eHA, eLA, out);

    for (int t = 1; t <= 10; t++) {
        const __nv_bfloat16* eHc = (t & 1) ? eHA : eHB;
        const __nv_bfloat16* eLc = (t & 1) ? eLA : eLB;
        __nv_bfloat16* eHn = (t & 1) ? eHB : eHA;
        __nv_bfloat16* eLn = (t & 1) ? eLB : eLA;
        const int* vc = (t == 1) ? x : ((t & 1) ? vB : vA);
        int*       vn = (t & 1) ? vA : vB;
        iter_mma<<<smcount, THREADS, SMEM_BYTES>>>(
            eHc, eLc, vc, eHn, eLn, vn,
            cnW1, cnb1, cnW2, cnb2,
            bnW1, bnb1, bnW2, bnb2,
            lab, llrW, llrb, out, t);
    }
}

// round 9
// speedup vs baseline: 3.8140x; 1.5546x over previous
#include <cuda_runtime.h>
#include <cuda_fp16.h>
#include <math.h>
#include <stdint.h>

#define Bb 256
#define Nn 1024
#define TILE_P 128
#define NTILES 1024
#define THREADS 512

// output buffer offsets (floats)
#define LOFF 0
#define POFF (Bb*11*Nn)
#define NOFF (POFF + Bb*Nn*11*2)

// smem byte offsets. X: 2 bufs x 128 rows x 256B (fp16, swizzled 16B chunks)
#define OX0  0
#define OW1H 65536
#define OW1L 98304
#define OW2H 131072
#define OW2L 147456
#define OBIG 163840
#define OS_B1 (OBIG + 0)
#define OS_B2 (OBIG + 512)
#define OS_LW (OBIG + 1024)
#define OS_C  (OBIG + 1536)
#define OS_LB (OBIG + 2048)
#define OS_VX (OBIG + 2056)
#define OS_VE (OBIG + 2312)
#define SMEM_BYTES (OBIG + 2568)

__device__ __align__(256) __half g_eA[Bb*Nn*64];
__device__ __align__(256) __half g_eB[Bb*Nn*64];
__device__ int g_vA[Bb*Nn];
__device__ int g_vB[Bb*Nn];

// ---------------------------------------------------------------------------
__device__ __forceinline__ uint32_t su32(const void* p) {
    uint32_t a;
    asm("{ .reg .u64 t; cvta.to.shared.u64 t, %1; cvt.u32.u64 %0, t; }" : "=r"(a) : "l"(p));
    return a;
}
__device__ __forceinline__ void ldsm4(uint32_t* r, uint32_t addr) {
    asm volatile("ldmatrix.sync.aligned.m8n8.x4.shared.b16 {%0,%1,%2,%3}, [%4];"
        : "=r"(r[0]), "=r"(r[1]), "=r"(r[2]), "=r"(r[3]) : "r"(addr));
}
__device__ __forceinline__ void ldsm4t(uint32_t* r, uint32_t addr) {
    asm volatile("ldmatrix.sync.aligned.m8n8.x4.trans.shared.b16 {%0,%1,%2,%3}, [%4];"
        : "=r"(r[0]), "=r"(r[1]), "=r"(r[2]), "=r"(r[3]) : "r"(addr));
}
__device__ __forceinline__ void mma16816(float* c, const uint32_t* a, uint32_t b0, uint32_t b1) {
    asm volatile("mma.sync.aligned.m16n8k16.row.col.f32.f16.f16.f32 "
        "{%0,%1,%2,%3}, {%4,%5,%6,%7}, {%8,%9}, {%0,%1,%2,%3};"
        : "+f"(c[0]), "+f"(c[1]), "+f"(c[2]), "+f"(c[3])
        : "r"(a[0]), "r"(a[1]), "r"(a[2]), "r"(a[3]), "r"(b0), "r"(b1));
}
__device__ __forceinline__ void splith(float v, __half& h, __half& l) {
    h = __float2half_rn(v);
    l = __float2half_rn(v - __half2float(h));
}
__device__ __forceinline__ uint32_t packh(__half a, __half b) {
    __half2 t; t.x = a; t.y = b;
    return *(uint32_t*)&t;
}
__device__ __forceinline__ uint32_t packf16(float a, float b) {
    __half2 t = __floats2half2_rn(a, b);
    return *(uint32_t*)&t;
}
__device__ __forceinline__ void cpa16(uint32_t dst, const void* src) {
    asm volatile("cp.async.cg.shared.global [%0], [%1], 16;" :: "r"(dst), "l"(src));
}
// swizzled byte offset of 16B chunk c16 in row r (256B rows)
__device__ __forceinline__ uint32_t swz(int r, int c16) {
    return (uint32_t)((r << 8) + (((c16 & 8) | ((c16 ^ r) & 7)) << 4));
}

// ---------------------------------------------------------------------------
// Stage 0
// ---------------------------------------------------------------------------
__global__ void stage0_kernel(const int* __restrict__ x, const float* __restrict__ y,
                              const float* __restrict__ embW, const float* __restrict__ embB,
                              const float* __restrict__ llrW, const float* __restrict__ llrb,
                              __half* __restrict__ e0, float* __restrict__ out)
{
    __shared__ float sE[128*65];
    __shared__ float sWe[128], sBe[64], sLW[128], sLB[2];
    const int tid = threadIdx.x;
    if (tid < 128) sWe[tid] = embW[tid];
    if (tid < 64)  sBe[tid] = embB[tid];
    if (tid < 128) sLW[tid] = llrW[tid];
    if (tid < 2)   sLB[tid] = llrb[tid];
    __syncthreads();

    const int gi = blockIdx.x * 128 + tid;
    const int b  = gi >> 10;
    const int n0 = gi & 1023;
    const float y0 = y[2*gi], y1 = y[2*gi+1];

    float ss = 0.f, l0 = sLB[0], l1 = sLB[1];
    #pragma unroll 8
    for (int d = 0; d < 64; d++) {
        float e = fmaf(y0, sWe[d], fmaf(y1, sWe[64+d], sBe[d]));
        ss = fmaf(e, e, ss);
        l0 = fmaf(e, sLW[2*d], l0);
        l1 = fmaf(e, sLW[2*d+1], l1);
        sE[tid*65 + d] = e;
    }
    float m = fmaxf(l0, l1);
    float x0 = expf(l0 - m), x1 = expf(l1 - m);
    float inv = 1.f / (x0 + x1);
    float p0 = x0 * inv, p1 = x1 * inv;
    int vv = x[gi];
    float pt = vv ? p1 : p0;
    pt = fminf(fmaxf(pt, 1e-7f), 1.0f);
    out[LOFF + (b*11 + 0)*Nn + n0] = -logf(pt);
    float* po = out + POFF + (((size_t)(b*Nn + n0))*11 + 0)*2;
    po[0] = p0; po[1] = p1;
    out[NOFF + (b*11 + 0)*Nn + n0] = sqrtf(ss);
    __syncthreads();

    uint32_t* dH = (uint32_t*)(e0 + (size_t)blockIdx.x * 128 * 64);
    for (int i = tid; i < 128*32; i += 128) {
        int row = i >> 5, q = i & 31;
        dH[i] = packf16(sE[row*65 + 2*q], sE[row*65 + 2*q + 1]);
    }
}

// ---------------------------------------------------------------------------
// Butterfly stage: fp16 asymmetric 2-pass mma.sync (A single, W hi+lo)
// ---------------------------------------------------------------------------
__global__ void __launch_bounds__(THREADS, 1)
iter_mma(const __half* __restrict__ eHc, const int* __restrict__ v_cur,
         __half* __restrict__ eHn, int* __restrict__ v_next,
         const float* __restrict__ cnW1, const float* __restrict__ cnb1,
         const float* __restrict__ cnW2, const float* __restrict__ cnb2,
         const float* __restrict__ bnW1, const float* __restrict__ bnb1,
         const float* __restrict__ bnW2, const float* __restrict__ bnb2,
         const float* __restrict__ lab,  const float* __restrict__ llrW,
         const float* __restrict__ llrb, float* __restrict__ out, int t)
{
    extern __shared__ char sm[];
    const uint32_t sbase = su32(sm);
    float* sB1 = (float*)(sm + OS_B1);
    float* sB2 = (float*)(sm + OS_B2);
    float* sLW = (float*)(sm + OS_LW);
    float* sC  = (float*)(sm + OS_C);
    float* sLB = (float*)(sm + OS_LB);
    uint8_t* sVx = (uint8_t*)(sm + OS_VX);
    uint8_t* sVe = (uint8_t*)(sm + OS_VE);

    const int tid  = threadIdx.x;
    const int wid  = tid >> 5, lane = tid & 31;
    const int wr   = wid & 7,  wc   = wid >> 3;
    const int lq   = lane & 3, lg   = lane >> 2;
    const int l15  = lane & 15;
    const int hi8  = lane >> 4;
    const int rx   = l15 & 7;

    // ---- stage weights -> smem (fp16 hi/lo, swizzled 256B rows) ----
    for (int i = tid; i < 128*128; i += THREADS) {
        int k = i >> 7, f = i & 127;
        float v = (f < 64) ? cnW1[k*64 + f] : bnW1[k*64 + (f - 64)];
        __half h, l; splith(v, h, l);
        uint32_t o = swz(k, f >> 3) + (f & 7)*2;
        *(__half*)(sm + OW1H + o) = h;
        *(__half*)(sm + OW1L + o) = l;
    }
    for (int i = tid; i < 64*128; i += THREADS) {
        int k = i >> 7, n = i & 127;
        float v = (n < 64) ? cnW2[k*64 + n] : bnW2[k*64 + (n - 64)];
        __half h, l; splith(v, h, l);
        uint32_t o = swz(k, n >> 3) + (n & 7)*2;
        *(__half*)(sm + OW2H + o) = h;
        *(__half*)(sm + OW2L + o) = l;
    }
    if (tid < 128) {
        sB1[tid] = (tid < 64) ? cnb1[tid] : bnb1[tid - 64];
        sB2[tid] = (tid < 64) ? cnb2[tid] : bnb2[tid - 64];
        sLW[tid] = llrW[tid];
    }
    if (tid < 2) sLB[tid] = llrb[tid];
    if (tid < 128) {
        int j = tid >> 6, f = tid & 63;
        float s = 0.f;
        for (int k = 0; k < 64; k++) s = fmaf(lab[j*64 + k], bnW1[(128 + k)*64 + f], s);
        sC[tid] = s;
    }

    const int hs    = 1 << (t - 1);
    const int shl   = t - 1;
    const int jmask = hs - 1;
    const int mlo = 16*wr + lg, mhi = mlo + 8;
    const uint32_t aArow = (uint32_t)((16*wr + l15) << 8);
    uint32_t bswz[4];
    #pragma unroll
    for (int ntp = 0; ntp < 4; ntp++) {
        int cb = 8*wc + 2*ntp + hi8;
        bswz[ntp] = (uint32_t)((((cb & 8) | ((cb ^ rx) & 7))) << 4);
    }

    // ---- tile issue: cp.async gather of X (fp16) + v loads ----
    auto issue = [&](int tile, int buf) {
        if (tile < NTILES) {
            const int pg0 = tile * TILE_P;
            const int b   = pg0 >> 9;
            const int pp0 = pg0 & 511;
            const __half* ehb = eHc + (size_t)b * (Nn*64);
            const uint32_t xh = sbase + buf*32768;
            #pragma unroll
            for (int ii = 0; ii < 4; ii++) {
                int i = tid + ii*THREADS;          // 2048 chunks
                int r = i >> 4, c16 = i & 15;
                int pp = pp0 + r;
                int oddn = ((pp >> shl) << t) + (pp & jmask);
                int n = oddn + ((c16 >> 3) ? hs : 0);
                cpa16(xh + swz(r, c16), (const char*)ehb + (size_t)n*128 + (c16 & 7)*16);
            }
            if (tid < 128) {
                int pp = pp0 + tid;
                int oddn = ((pp >> shl) << t) + (pp & jmask);
                int vo = v_cur[b*Nn + oddn];
                int ve = v_cur[b*Nn + oddn + hs];
                sVx[buf*128 + tid] = (uint8_t)((vo + ve) & 1);
                sVe[buf*128 + tid] = (uint8_t)ve;
            }
        }
        asm volatile("cp.async.commit_group;" ::: "memory");
    };

    int buf = 0;
    __syncthreads();                    // weights + sC ready before first compute
    issue((int)blockIdx.x, 0);

    for (int tile = blockIdx.x; tile < NTILES; tile += gridDim.x) {
        issue(tile + (int)gridDim.x, buf ^ 1);
        asm volatile("cp.async.wait_group 1;" ::: "memory");
        __syncthreads();

        const int pg0 = tile * TILE_P;
        const int b   = pg0 >> 9;
        const int pp0 = pg0 & 511;
        const uint32_t xbase = sbase + buf*32768;

        // ---- GEMM1: acc1 = X @ W1cat (A single fp16, W hi+lo) ----
        float acc1[8][4];
        #pragma unroll
        for (int i = 0; i < 8; i++)
            #pragma unroll
            for (int j = 0; j < 4; j++) acc1[i][j] = 0.f;

        #pragma unroll
        for (int kt = 0; kt < 8; kt++) {
            int ch = 2*kt + hi8;
            uint32_t ah[4];
            ldsm4(ah, xbase + aArow + ((((ch & 8) | ((ch ^ rx) & 7))) << 4));
            uint32_t brow = sbase + OW1H + (uint32_t)((16*kt + l15) << 8);
            #pragma unroll
            for (int ntp = 0; ntp < 4; ntp++) {
                uint32_t bh[4], bl[4];
                uint32_t ba = brow + bswz[ntp];
                ldsm4t(bh, ba);
                ldsm4t(bl, ba + (OW1L - OW1H));
                mma16816(acc1[2*ntp],   ah, bh[0], bh[1]);
                mma16816(acc1[2*ntp],   ah, bl[0], bl[1]);
                mma16816(acc1[2*ntp+1], ah, bh[2], bh[3]);
                mma16816(acc1[2*ntp+1], ah, bl[2], bl[3]);
            }
        }

        // ---- H epilogue in registers: bias + c_vx + relu, cvt fp16 ----
        const int vxlo = sVx[buf*128 + mlo], vxhi = sVx[buf*128 + mhi];
        uint32_t pH0[8], pH1[8];
        #pragma unroll
        for (int nt = 0; nt < 8; nt++) {
            int d0 = 8*nt + 2*lq;
            int f0 = 64*wc + d0;
            float h00 = acc1[nt][0] + sB1[f0];
            float h01 = acc1[nt][1] + sB1[f0+1];
            float h10 = acc1[nt][2] + sB1[f0];
            float h11 = acc1[nt][3] + sB1[f0+1];
            if (wc) {
                h00 += sC[vxlo*64 + d0];  h01 += sC[vxlo*64 + d0 + 1];
                h10 += sC[vxhi*64 + d0];  h11 += sC[vxhi*64 + d0 + 1];
            }
            pH0[nt] = packf16(fmaxf(h00, 0.f), fmaxf(h01, 0.f));
            pH1[nt] = packf16(fmaxf(h10, 0.f), fmaxf(h11, 0.f));
        }

        // ---- GEMM2: acc2 = H @ W2block (A from registers, W hi+lo) ----
        float acc2[8][4];
        #pragma unroll
        for (int i = 0; i < 8; i++)
            #pragma unroll
            for (int j = 0; j < 4; j++) acc2[i][j] = 0.f;

        #pragma unroll
        for (int kt = 0; kt < 4; kt++) {
            uint32_t a2[4] = {pH0[2*kt], pH1[2*kt], pH0[2*kt+1], pH1[2*kt+1]};
            uint32_t brow = sbase + OW2H + (uint32_t)((16*kt + l15) << 8);
            #pragma unroll
            for (int ntp = 0; ntp < 4; ntp++) {
                uint32_t bh[4], bl[4];
                uint32_t ba = brow + bswz[ntp];
                ldsm4t(bh, ba);
                ldsm4t(bl, ba + (OW2L - OW2H));
                mma16816(acc2[2*ntp],   a2, bh[0], bh[1]);
                mma16816(acc2[2*ntp],   a2, bl[0], bl[1]);
                mma16816(acc2[2*ntp+1], a2, bh[2], bh[3]);
                mma16816(acc2[2*ntp+1], a2, bl[2], bl[3]);
            }
        }

        // ---- output epilogue ----
        float pssL = 0.f, pl0L = 0.f, pl1L = 0.f;
        float pssH = 0.f, pl0H = 0.f, pl1H = 0.f;
        #pragma unroll
        for (int nt = 0; nt < 8; nt++) {
            int d0 = 8*nt + 2*lq;
            int f0 = 64*wc + d0;
            float e00 = acc2[nt][0] + sB2[f0];
            float e01 = acc2[nt][1] + sB2[f0+1];
            float e10 = acc2[nt][2] + sB2[f0];
            float e11 = acc2[nt][3] + sB2[f0+1];
            acc2[nt][0] = e00; acc2[nt][1] = e01;
            acc2[nt][2] = e10; acc2[nt][3] = e11;
            pssL = fmaf(e00,e00, fmaf(e01,e01, pssL));
            pssH = fmaf(e10,e10, fmaf(e11,e11, pssH));
            pl0L = fmaf(e00, sLW[2*d0],   fmaf(e01, sLW[2*d0+2], pl0L));
            pl1L = fmaf(e00, sLW[2*d0+1], fmaf(e01, sLW[2*d0+3], pl1L));
            pl0H = fmaf(e10, sLW[2*d0],   fmaf(e11, sLW[2*d0+2], pl0H));
            pl1H = fmaf(e10, sLW[2*d0+1], fmaf(e11, sLW[2*d0+3], pl1H));
        }
        #pragma unroll
        for (int off = 1; off <= 2; off <<= 1) {
            pssL += __shfl_xor_sync(0xffffffffu, pssL, off);
            pl0L += __shfl_xor_sync(0xffffffffu, pl0L, off);
            pl1L += __shfl_xor_sync(0xffffffffu, pl1L, off);
            pssH += __shfl_xor_sync(0xffffffffu, pssH, off);
            pl0H += __shfl_xor_sync(0xffffffffu, pl0H, off);
            pl1H += __shfl_xor_sync(0xffffffffu, pl1H, off);
        }
        if (lq == 0) {
            #pragma unroll
            for (int half = 0; half < 2; half++) {
                int p   = half ? mhi : mlo;
                float ss = half ? pssH : pssL;
                float l0 = (half ? pl0H : pl0L) + sLB[0];
                float l1 = (half ? pl1H : pl1L) + sLB[1];
                float m = fmaxf(l0, l1);
                float x0 = expf(l0 - m), x1 = expf(l1 - m);
                float inv = 1.f / (x0 + x1);
                float p0 = x0 * inv, p1 = x1 * inv;
                int vv = wc ? (int)sVe[buf*128 + p] : (int)sVx[buf*128 + p];
                float pt = vv ? p1 : p0;
                pt = fminf(fmaxf(pt, 1e-7f), 1.0f);
                int n = 2*(pp0 + p) + wc;
                out[LOFF + (b*11 + t)*Nn + n] = -logf(pt);
                float* po = out + POFF + (((size_t)(b*Nn + n))*11 + t)*2;
                po[0] = p0; po[1] = p1;
                out[NOFF + (b*11 + t)*Nn + n] = sqrtf(ss);
                v_next[b*Nn + n] = vv;
            }
        }
        {
            size_t rlo = ((size_t)b*Nn + 2*(pp0 + mlo) + wc)*64;
            size_t rhi = ((size_t)b*Nn + 2*(pp0 + mhi) + wc)*64;
            #pragma unroll
            for (int nt = 0; nt < 8; nt++) {
                int d0 = 8*nt + 2*lq;
                *(uint32_t*)(eHn + rlo + d0) = packf16(acc2[nt][0], acc2[nt][1]);
                *(uint32_t*)(eHn + rhi + d0) = packf16(acc2[nt][2], acc2[nt][3]);
            }
        }
        __syncthreads();
        buf ^= 1;
    }
}

// ---------------------------------------------------------------------------
extern "C" void kernel_launch(void* const* d_in, const int* in_sizes, int n_in,
                              void* d_out, int out_size)
{
    const int*   x     = (const int*)  d_in[0];
    const float* y     = (const float*)d_in[1];
    const float* embW  = (const float*)d_in[2];
    const float* embB  = (const float*)d_in[3];
    const float* lab   = (const float*)d_in[4];
    const float* cnW1  = (const float*)d_in[5];
    const float* cnb1  = (const float*)d_in[6];
    const float* cnW2  = (const float*)d_in[7];
    const float* cnb2  = (const float*)d_in[8];
    const float* bnW1  = (const float*)d_in[9];
    const float* bnb1  = (const float*)d_in[10];
    const float* bnW2  = (const float*)d_in[11];
    const float* bnb2  = (const float*)d_in[12];
    const float* llrW  = (const float*)d_in[13];
    const float* llrb  = (const float*)d_in[14];
    float* out = (float*)d_out;

    __half *eA, *eB; int *vA, *vB;
    cudaGetSymbolAddress((void**)&eA, g_eA);
    cudaGetSymbolAddress((void**)&eB, g_eB);
    cudaGetSymbolAddress((void**)&vA, g_vA);
    cudaGetSymbolAddress((void**)&vB, g_vB);

    int smcount = 148;
    cudaDeviceGetAttribute(&smcount, cudaDevAttrMultiProcessorCount, 0);
    cudaFuncSetAttribute(iter_mma, cudaFuncAttributeMaxDynamicSharedMemorySize, SMEM_BYTES);

    stage0_kernel<<<(Bb*Nn)/128, 128>>>(x, y, embW, embB, llrW, llrb, eA, out);

    for (int t = 1; t <= 10; t++) {
        const __half* ec = (t & 1) ? eA : eB;
        __half*       en = (t & 1) ? eB : eA;
        const int* vc = (t == 1) ? x : ((t & 1) ? vB : vA);
        int*       vn = (t & 1) ? vA : vB;
        iter_mma<<<smcount, THREADS, SMEM_BYTES>>>(
            ec, vc, en, vn,
            cnW1, cnb1, cnW2, cnb2,
            bnW1, bnb1, bnW2, bnb2,
            lab, llrW, llrb, out, t);
    }
}

// round 10
// speedup vs baseline: 4.2218x; 1.1069x over previous
#include <cuda_runtime.h>
#include <cuda_fp16.h>
#include <math.h>
#include <stdint.h>

#define Bb 256
#define Nn 1024
#define TILE_P 128
#define NTILES 1024
#define THREADS 256

// output buffer offsets (floats)
#define LOFF 0
#define POFF (Bb*11*Nn)
#define NOFF (POFF + Bb*Nn*11*2)

// smem layout (bytes). X: 2 bufs x 128 rows x 256B. W rows are 128B (64 fp16).
#define OX0  0
#define OW1H 65536
#define OW1L 81920
#define OW2H 98304
#define OBIG 106496
#define OS_C2 (OBIG + 0)       // 2 x 64 floats: b1 + c_vx (bn) / b1 (cn)
#define OS_B2 (OBIG + 512)     // 64 floats
#define OS_LW (OBIG + 768)     // 128 floats
#define OS_LB (OBIG + 1280)    // 2 floats
#define OS_VX (OBIG + 1288)    // 2 bufs x 128
#define OS_VE (OBIG + 1544)
#define SMEM_BYTES (OBIG + 1800)

__device__ __align__(256) __half g_eA[Bb*Nn*64];
__device__ __align__(256) __half g_eB[Bb*Nn*64];
__device__ int g_vA[Bb*Nn];
__device__ int g_vB[Bb*Nn];

// ---------------------------------------------------------------------------
__device__ __forceinline__ uint32_t su32(const void* p) {
    uint32_t a;
    asm("{ .reg .u64 t; cvta.to.shared.u64 t, %1; cvt.u32.u64 %0, t; }" : "=r"(a) : "l"(p));
    return a;
}
__device__ __forceinline__ void ldsm4(uint32_t* r, uint32_t addr) {
    asm volatile("ldmatrix.sync.aligned.m8n8.x4.shared.b16 {%0,%1,%2,%3}, [%4];"
        : "=r"(r[0]), "=r"(r[1]), "=r"(r[2]), "=r"(r[3]) : "r"(addr));
}
__device__ __forceinline__ void ldsm4t(uint32_t* r, uint32_t addr) {
    asm volatile("ldmatrix.sync.aligned.m8n8.x4.trans.shared.b16 {%0,%1,%2,%3}, [%4];"
        : "=r"(r[0]), "=r"(r[1]), "=r"(r[2]), "=r"(r[3]) : "r"(addr));
}
__device__ __forceinline__ void mma16816(float* c, const uint32_t* a, uint32_t b0, uint32_t b1) {
    asm volatile("mma.sync.aligned.m16n8k16.row.col.f32.f16.f16.f32 "
        "{%0,%1,%2,%3}, {%4,%5,%6,%7}, {%8,%9}, {%0,%1,%2,%3};"
        : "+f"(c[0]), "+f"(c[1]), "+f"(c[2]), "+f"(c[3])
        : "r"(a[0]), "r"(a[1]), "r"(a[2]), "r"(a[3]), "r"(b0), "r"(b1));
}
__device__ __forceinline__ void splith(float v, __half& h, __half& l) {
    h = __float2half_rn(v);
    l = __float2half_rn(v - __half2float(h));
}
__device__ __forceinline__ uint32_t packf16(float a, float b) {
    __half2 t = __floats2half2_rn(a, b);
    return *(uint32_t*)&t;
}
__device__ __forceinline__ void cpa16(uint32_t dst, const void* src) {
    asm volatile("cp.async.cg.shared.global [%0], [%1], 16;" :: "r"(dst), "l"(src));
}
// X swizzle: 256B rows, 16 chunks
__device__ __forceinline__ uint32_t swz(int r, int c16) {
    return (uint32_t)((r << 8) + (((c16 & 8) | ((c16 ^ r) & 7)) << 4));
}
// W swizzle: 128B rows, 8 chunks
__device__ __forceinline__ uint32_t swz128(int r, int c16) {
    return (uint32_t)((r << 7) + (((c16 ^ r) & 7) << 4));
}

// ---------------------------------------------------------------------------
// Stage 0
// ---------------------------------------------------------------------------
__global__ void stage0_kernel(const int* __restrict__ x, const float* __restrict__ y,
                              const float* __restrict__ embW, const float* __restrict__ embB,
                              const float* __restrict__ llrW, const float* __restrict__ llrb,
                              __half* __restrict__ e0, float* __restrict__ out)
{
    __shared__ float sE[128*65];
    __shared__ float sWe[128], sBe[64], sLW[128], sLB[2];
    const int tid = threadIdx.x;
    if (tid < 128) sWe[tid] = embW[tid];
    if (tid < 64)  sBe[tid] = embB[tid];
    if (tid < 128) sLW[tid] = llrW[tid];
    if (tid < 2)   sLB[tid] = llrb[tid];
    __syncthreads();

    const int gi = blockIdx.x * 128 + tid;
    const int b  = gi >> 10;
    const int n0 = gi & 1023;
    const float y0 = y[2*gi], y1 = y[2*gi+1];

    float ss = 0.f, l0 = sLB[0], l1 = sLB[1];
    #pragma unroll 8
    for (int d = 0; d < 64; d++) {
        float e = fmaf(y0, sWe[d], fmaf(y1, sWe[64+d], sBe[d]));
        ss = fmaf(e, e, ss);
        l0 = fmaf(e, sLW[2*d], l0);
        l1 = fmaf(e, sLW[2*d+1], l1);
        sE[tid*65 + d] = e;
    }
    float m = fmaxf(l0, l1);
    float x0 = expf(l0 - m), x1 = expf(l1 - m);
    float inv = 1.f / (x0 + x1);
    float p0 = x0 * inv, p1 = x1 * inv;
    int vv = x[gi];
    float pt = vv ? p1 : p0;
    pt = fminf(fmaxf(pt, 1e-7f), 1.0f);
    out[LOFF + (b*11 + 0)*Nn + n0] = -logf(pt);
    float* po = out + POFF + (((size_t)(b*Nn + n0))*11 + 0)*2;
    po[0] = p0; po[1] = p1;
    out[NOFF + (b*11 + 0)*Nn + n0] = sqrtf(ss);
    __syncthreads();

    uint32_t* dH = (uint32_t*)(e0 + (size_t)blockIdx.x * 128 * 64);
    for (int i = tid; i < 128*32; i += 128) {
        int row = i >> 5, q = i & 31;
        dH[i] = packf16(sE[row*65 + 2*q], sE[row*65 + 2*q + 1]);
    }
}

// ---------------------------------------------------------------------------
// Butterfly stage, half-split: CTA parity hf=0 computes cn/even outputs,
// hf=1 computes bn/odd outputs. 256 threads, 2 CTAs/SM.
// GEMM1: A single fp16, W1 hi+lo (2-pass). GEMM2: single pass.
// ---------------------------------------------------------------------------
__global__ void __launch_bounds__(THREADS, 2)
iter_mma(const __half* __restrict__ eHc, const int* __restrict__ v_cur,
         __half* __restrict__ eHn, int* __restrict__ v_next,
         const float* __restrict__ cnW1, const float* __restrict__ cnb1,
         const float* __restrict__ cnW2, const float* __restrict__ cnb2,
         const float* __restrict__ bnW1, const float* __restrict__ bnb1,
         const float* __restrict__ bnW2, const float* __restrict__ bnb2,
         const float* __restrict__ lab,  const float* __restrict__ llrW,
         const float* __restrict__ llrb, float* __restrict__ out, int t)
{
    extern __shared__ char sm[];
    const uint32_t sbase = su32(sm);
    float* sC2 = (float*)(sm + OS_C2);
    float* sB2 = (float*)(sm + OS_B2);
    float* sLW = (float*)(sm + OS_LW);
    float* sLB = (float*)(sm + OS_LB);
    uint8_t* sVx = (uint8_t*)(sm + OS_VX);
    uint8_t* sVe = (uint8_t*)(sm + OS_VE);

    const int tid  = threadIdx.x;
    const int wid  = tid >> 5, lane = tid & 31;
    const int wr   = wid;              // 8 warps: 16 rows each
    const int hf   = blockIdx.x & 1;   // 0: cn/even, 1: bn/odd
    const int lq   = lane & 3, lg   = lane >> 2;
    const int l15  = lane & 15;
    const int hi8  = lane >> 4;
    const int rx   = l15 & 7;

    // ---- stage weights -> smem ----
    const float* W1s = hf ? bnW1 : cnW1;
    const float* W2s = hf ? bnW2 : cnW2;
    const float* b1s = hf ? bnb1 : cnb1;
    const float* b2s = hf ? bnb2 : cnb2;
    for (int i = tid; i < 128*64; i += THREADS) {
        int k = i >> 6, f = i & 63;
        float v = W1s[k*64 + f];
        __half h, l; splith(v, h, l);
        uint32_t o = swz128(k, f >> 3) + (f & 7)*2;
        *(__half*)(sm + OW1H + o) = h;
        *(__half*)(sm + OW1L + o) = l;
    }
    for (int i = tid; i < 64*64; i += THREADS) {
        int k = i >> 6, f = i & 63;
        uint32_t o = swz128(k, f >> 3) + (f & 7)*2;
        *(__half*)(sm + OW2H + o) = __float2half_rn(W2s[k*64 + f]);
    }
    if (tid < 64) sB2[tid] = b2s[tid];
    if (tid < 128) sLW[tid] = llrW[tid];
    if (tid < 2)   sLB[tid] = llrb[tid];
    if (tid < 128) {                   // sC2[j][f] = b1[f] (+ lab[j]·bnW1[128:192] if bn)
        int j = tid >> 6, f = tid & 63;
        float s = b1s[f];
        if (hf) {
            for (int k = 0; k < 64; k++) s = fmaf(lab[j*64 + k], bnW1[(128 + k)*64 + f], s);
        }
        sC2[j*64 + f] = s;
    }

    const int hs    = 1 << (t - 1);
    const int shl   = t - 1;
    const int jmask = hs - 1;
    const int mlo = 16*wr + lg, mhi = mlo + 8;
    const uint32_t aArow = (uint32_t)((16*wr + l15) << 8);
    uint32_t bswz[4];
    #pragma unroll
    for (int ntp = 0; ntp < 4; ntp++)
        bswz[ntp] = (uint32_t)((((2*ntp + hi8) ^ rx) & 7) << 4);

    const int tstep = (int)(gridDim.x >> 1);

    // ---- tile issue: cp.async gather of X + v loads ----
    auto issue = [&](int tile, int buf) {
        if (tile < NTILES) {
            const int pg0 = tile * TILE_P;
            const int b   = pg0 >> 9;
            const int pp0 = pg0 & 511;
            const __half* ehb = eHc + (size_t)b * (Nn*64);
            const uint32_t xh = sbase + buf*32768;
            #pragma unroll
            for (int ii = 0; ii < 8; ii++) {
                int i = tid + ii*THREADS;          // 2048 chunks
                int r = i >> 4, c16 = i & 15;
                int pp = pp0 + r;
                int oddn = ((pp >> shl) << t) + (pp & jmask);
                int n = oddn + ((c16 >> 3) ? hs : 0);
                cpa16(xh + swz(r, c16), (const char*)ehb + (size_t)n*128 + (c16 & 7)*16);
            }
            if (tid < 128) {
                int pp = pp0 + tid;
                int oddn = ((pp >> shl) << t) + (pp & jmask);
                int vo = v_cur[b*Nn + oddn];
                int ve = v_cur[b*Nn + oddn + hs];
                sVx[buf*128 + tid] = (uint8_t)((vo + ve) & 1);
                sVe[buf*128 + tid] = (uint8_t)ve;
            }
        }
        asm volatile("cp.async.commit_group;" ::: "memory");
    };

    int buf = 0;
    __syncthreads();
    issue((int)(blockIdx.x >> 1), 0);

    for (int tile = (int)(blockIdx.x >> 1); tile < NTILES; tile += tstep) {
        issue(tile + tstep, buf ^ 1);
        asm volatile("cp.async.wait_group 1;" ::: "memory");
        __syncthreads();

        const int pg0 = tile * TILE_P;
        const int b   = pg0 >> 9;
        const int pp0 = pg0 & 511;
        const uint32_t xbase = sbase + buf*32768;

        // ---- GEMM1: acc1[16 rows x 64 f] = X @ W1half^T (W hi+lo) ----
        float acc1[8][4];
        #pragma unroll
        for (int i = 0; i < 8; i++)
            #pragma unroll
            for (int j = 0; j < 4; j++) acc1[i][j] = 0.f;

        #pragma unroll
        for (int kt = 0; kt < 8; kt++) {
            int ch = 2*kt + hi8;
            uint32_t ah[4];
            ldsm4(ah, xbase + aArow + ((((ch & 8) | ((ch ^ rx) & 7))) << 4));
            uint32_t brow = sbase + OW1H + (uint32_t)((16*kt + l15) << 7);
            #pragma unroll
            for (int ntp = 0; ntp < 4; ntp++) {
                uint32_t bh[4], bl[4];
                uint32_t ba = brow + bswz[ntp];
                ldsm4t(bh, ba);
                ldsm4t(bl, ba + (OW1L - OW1H));
                mma16816(acc1[2*ntp],   ah, bh[0], bh[1]);
                mma16816(acc1[2*ntp],   ah, bl[0], bl[1]);
                mma16816(acc1[2*ntp+1], ah, bh[2], bh[3]);
                mma16816(acc1[2*ntp+1], ah, bl[2], bl[3]);
            }
        }

        // ---- H epilogue: (bias + c_vx) + relu, cvt fp16 ----
        const int vxlo = sVx[buf*128 + mlo], vxhi = sVx[buf*128 + mhi];
        uint32_t pH0[8], pH1[8];
        #pragma unroll
        for (int nt = 0; nt < 8; nt++) {
            int d0 = 8*nt + 2*lq;
            float h00 = acc1[nt][0] + sC2[vxlo*64 + d0];
            float h01 = acc1[nt][1] + sC2[vxlo*64 + d0 + 1];
            float h10 = acc1[nt][2] + sC2[vxhi*64 + d0];
            float h11 = acc1[nt][3] + sC2[vxhi*64 + d0 + 1];
            pH0[nt] = packf16(fmaxf(h00, 0.f), fmaxf(h01, 0.f));
            pH1[nt] = packf16(fmaxf(h10, 0.f), fmaxf(h11, 0.f));
        }

        // ---- GEMM2: acc2 = H @ W2half^T (single pass) ----
        float acc2[8][4];
        #pragma unroll
        for (int i = 0; i < 8; i++)
            #pragma unroll
            for (int j = 0; j < 4; j++) acc2[i][j] = 0.f;

        #pragma unroll
        for (int kt = 0; kt < 4; kt++) {
            uint32_t a2[4] = {pH0[2*kt], pH1[2*kt], pH0[2*kt+1], pH1[2*kt+1]};
            uint32_t brow = sbase + OW2H + (uint32_t)((16*kt + l15) << 7);
            #pragma unroll
            for (int ntp = 0; ntp < 4; ntp++) {
                uint32_t bh[4];
                ldsm4t(bh, brow + bswz[ntp]);
                mma16816(acc2[2*ntp],   a2, bh[0], bh[1]);
                mma16816(acc2[2*ntp+1], a2, bh[2], bh[3]);
            }
        }

        // ---- output epilogue ----
        float pssL = 0.f, pl0L = 0.f, pl1L = 0.f;
        float pssH = 0.f, pl0H = 0.f, pl1H = 0.f;
        #pragma unroll
        for (int nt = 0; nt < 8; nt++) {
            int d0 = 8*nt + 2*lq;
            float e00 = acc2[nt][0] + sB2[d0];
            float e01 = acc2[nt][1] + sB2[d0+1];
            float e10 = acc2[nt][2] + sB2[d0];
            float e11 = acc2[nt][3] + sB2[d0+1];
            acc2[nt][0] = e00; acc2[nt][1] = e01;
            acc2[nt][2] = e10; acc2[nt][3] = e11;
            pssL = fmaf(e00,e00, fmaf(e01,e01, pssL));
            pssH = fmaf(e10,e10, fmaf(e11,e11, pssH));
            pl0L = fmaf(e00, sLW[2*d0],   fmaf(e01, sLW[2*d0+2], pl0L));
            pl1L = fmaf(e00, sLW[2*d0+1], fmaf(e01, sLW[2*d0+3], pl1L));
            pl0H = fmaf(e10, sLW[2*d0],   fmaf(e11, sLW[2*d0+2], pl0H));
            pl1H = fmaf(e10, sLW[2*d0+1], fmaf(e11, sLW[2*d0+3], pl1H));
        }
        #pragma unroll
        for (int off = 1; off <= 2; off <<= 1) {
            pssL += __shfl_xor_sync(0xffffffffu, pssL, off);
            pl0L += __shfl_xor_sync(0xffffffffu, pl0L, off);
            pl1L += __shfl_xor_sync(0xffffffffu, pl1L, off);
            pssH += __shfl_xor_sync(0xffffffffu, pssH, off);
            pl0H += __shfl_xor_sync(0xffffffffu, pl0H, off);
            pl1H += __shfl_xor_sync(0xffffffffu, pl1H, off);
        }
        if (lq == 0) {
            #pragma unroll
            for (int half = 0; half < 2; half++) {
                int p   = half ? mhi : mlo;
                float ss = half ? pssH : pssL;
                float l0 = (half ? pl0H : pl0L) + sLB[0];
                float l1 = (half ? pl1H : pl1L) + sLB[1];
                float m = fmaxf(l0, l1);
                float x0 = expf(l0 - m), x1 = expf(l1 - m);
                float inv = 1.f / (x0 + x1);
                float p0 = x0 * inv, p1 = x1 * inv;
                int vv = hf ? (int)sVe[buf*128 + p] : (int)sVx[buf*128 + p];
                float pt = vv ? p1 : p0;
                pt = fminf(fmaxf(pt, 1e-7f), 1.0f);
                int n = 2*(pp0 + p) + hf;
                out[LOFF + (b*11 + t)*Nn + n] = -logf(pt);
                float* po = out + POFF + (((size_t)(b*Nn + n))*11 + t)*2;
                po[0] = p0; po[1] = p1;
                out[NOFF + (b*11 + t)*Nn + n] = sqrtf(ss);
                v_next[b*Nn + n] = vv;
            }
        }
        {
            size_t rlo = ((size_t)b*Nn + 2*(pp0 + mlo) + hf)*64;
            size_t rhi = ((size_t)b*Nn + 2*(pp0 + mhi) + hf)*64;
            #pragma unroll
            for (int nt = 0; nt < 8; nt++) {
                int d0 = 8*nt + 2*lq;
                *(uint32_t*)(eHn + rlo + d0) = packf16(acc2[nt][0], acc2[nt][1]);
                *(uint32_t*)(eHn + rhi + d0) = packf16(acc2[nt][2], acc2[nt][3]);
            }
        }
        __syncthreads();
        buf ^= 1;
    }
}

// ---------------------------------------------------------------------------
extern "C" void kernel_launch(void* const* d_in, const int* in_sizes, int n_in,
                              void* d_out, int out_size)
{
    const int*   x     = (const int*)  d_in[0];
    const float* y     = (const float*)d_in[1];
    const float* embW  = (const float*)d_in[2];
    const float* embB  = (const float*)d_in[3];
    const float* lab   = (const float*)d_in[4];
    const float* cnW1  = (const float*)d_in[5];
    const float* cnb1  = (const float*)d_in[6];
    const float* cnW2  = (const float*)d_in[7];
    const float* cnb2  = (const float*)d_in[8];
    const float* bnW1  = (const float*)d_in[9];
    const float* bnb1  = (const float*)d_in[10];
    const float* bnW2  = (const float*)d_in[11];
    const float* bnb2  = (const float*)d_in[12];
    const float* llrW  = (const float*)d_in[13];
    const float* llrb  = (const float*)d_in[14];
    float* out = (float*)d_out;

    __half *eA, *eB; int *vA, *vB;
    cudaGetSymbolAddress((void**)&eA, g_eA);
    cudaGetSymbolAddress((void**)&eB, g_eB);
    cudaGetSymbolAddress((void**)&vA, g_vA);
    cudaGetSymbolAddress((void**)&vB, g_vB);

    int smcount = 148;
    cudaDeviceGetAttribute(&smcount, cudaDevAttrMultiProcessorCount, 0);
    cudaFuncSetAttribute(iter_mma, cudaFuncAttributeMaxDynamicSharedMemorySize, SMEM_BYTES);

    stage0_kernel<<<(Bb*Nn)/128, 128>>>(x, y, embW, embB, llrW, llrb, eA, out);

    for (int t = 1; t <= 10; t++) {
        const __half* ec = (t & 1) ? eA : eB;
        __half*       en = (t & 1) ? eB : eA;
        const int* vc = (t == 1) ? x : ((t & 1) ? vB : vA);
        int*       vn = (t & 1) ? vA : vB;
        iter_mma<<<2*smcount, THREADS, SMEM_BYTES>>>(
            ec, vc, en, vn,
            cnW1, cnb1, cnW2, cnb2,
            bnW1, bnb1, bnW2, bnb2,
            lab, llrW, llrb, out, t);
    }
}

// round 12
// speedup vs baseline: 4.9741x; 1.1782x over previous
#include <cuda_runtime.h>
#include <cuda_fp16.h>
#include <math.h>
#include <stdint.h>

#define Bb 256
#define Nn 1024
#define TILE_P 128
#define NTILES 1024
#define THREADS 256

// output buffer offsets (floats)
#define LOFF 0
#define POFF (Bb*11*Nn)
#define NOFF (POFF + Bb*Nn*11*2)

// smem layout (bytes). X: 2 bufs x 128 rows x 256B. W rows are 128B (64 fp16).
#define OX0  0
#define OW1H 65536
#define OW2H 81920
#define OBIG 90112
#define OS_C2 (OBIG + 0)       // 2 x 64 floats: b1 + c_vx (bn) / b1 (cn)
#define OS_B2 (OBIG + 512)     // 64 floats
#define OS_LW (OBIG + 768)     // 128 floats
#define OS_LB (OBIG + 1280)    // 2 floats
#define OS_VX (OBIG + 1288)    // 2 bufs x 128
#define OS_VE (OBIG + 1544)
#define SMEM_BYTES (OBIG + 1800)

__device__ __align__(256) __half g_eA[Bb*Nn*64];
__device__ __align__(256) __half g_eB[Bb*Nn*64];
__device__ int g_vA[Bb*Nn];
__device__ int g_vB[Bb*Nn];

// ---------------------------------------------------------------------------
__device__ __forceinline__ uint32_t su32(const void* p) {
    uint32_t a;
    asm("{ .reg .u64 t; cvta.to.shared.u64 t, %1; cvt.u32.u64 %0, t; }" : "=r"(a) : "l"(p));
    return a;
}
__device__ __forceinline__ void ldsm4(uint32_t* r, uint32_t addr) {
    asm volatile("ldmatrix.sync.aligned.m8n8.x4.shared.b16 {%0,%1,%2,%3}, [%4];"
        : "=r"(r[0]), "=r"(r[1]), "=r"(r[2]), "=r"(r[3]) : "r"(addr));
}
__device__ __forceinline__ void ldsm4t(uint32_t* r, uint32_t addr) {
    asm volatile("ldmatrix.sync.aligned.m8n8.x4.trans.shared.b16 {%0,%1,%2,%3}, [%4];"
        : "=r"(r[0]), "=r"(r[1]), "=r"(r[2]), "=r"(r[3]) : "r"(addr));
}
__device__ __forceinline__ void mma16816(float* c, const uint32_t* a, uint32_t b0, uint32_t b1) {
    asm volatile("mma.sync.aligned.m16n8k16.row.col.f32.f16.f16.f32 "
        "{%0,%1,%2,%3}, {%4,%5,%6,%7}, {%8,%9}, {%0,%1,%2,%3};"
        : "+f"(c[0]), "+f"(c[1]), "+f"(c[2]), "+f"(c[3])
        : "r"(a[0]), "r"(a[1]), "r"(a[2]), "r"(a[3]), "r"(b0), "r"(b1));
}
__device__ __forceinline__ uint32_t packf16(float a, float b) {
    __half2 t = __floats2half2_rn(a, b);
    return *(uint32_t*)&t;
}
__device__ __forceinline__ void cpa16(uint32_t dst, const void* src) {
    asm volatile("cp.async.cg.shared.global [%0], [%1], 16;" :: "r"(dst), "l"(src));
}
// X swizzle: 256B rows, 16 chunks
__device__ __forceinline__ uint32_t swz(int r, int c16) {
    return (uint32_t)((r << 8) + (((c16 & 8) | ((c16 ^ r) & 7)) << 4));
}
// W swizzle: 128B rows, 8 chunks
__device__ __forceinline__ uint32_t swz128(int r, int c16) {
    return (uint32_t)((r << 7) + (((c16 ^ r) & 7) << 4));
}

// ---------------------------------------------------------------------------
// Stage 0
// ---------------------------------------------------------------------------
__global__ void stage0_kernel(const int* __restrict__ x, const float* __restrict__ y,
                              const float* __restrict__ embW, const float* __restrict__ embB,
                              const float* __restrict__ llrW, const float* __restrict__ llrb,
                              __half* __restrict__ e0, float* __restrict__ out)
{
    __shared__ float sE[128*65];
    __shared__ float sWe[128], sBe[64], sLW[128], sLB[2];
    const int tid = threadIdx.x;
    if (tid < 128) sWe[tid] = embW[tid];
    if (tid < 64)  sBe[tid] = embB[tid];
    if (tid < 128) sLW[tid] = llrW[tid];
    if (tid < 2)   sLB[tid] = llrb[tid];
    __syncthreads();

    const int gi = blockIdx.x * 128 + tid;
    const int b  = gi >> 10;
    const int n0 = gi & 1023;
    const float y0 = y[2*gi], y1 = y[2*gi+1];

    float ss = 0.f, l0 = sLB[0], l1 = sLB[1];
    #pragma unroll 8
    for (int d = 0; d < 64; d++) {
        float e = fmaf(y0, sWe[d], fmaf(y1, sWe[64+d], sBe[d]));
        ss = fmaf(e, e, ss);
        l0 = fmaf(e, sLW[2*d], l0);
        l1 = fmaf(e, sLW[2*d+1], l1);
        sE[tid*65 + d] = e;
    }
    float m = fmaxf(l0, l1);
    float x0 = expf(l0 - m), x1 = expf(l1 - m);
    float inv = 1.f / (x0 + x1);
    float p0 = x0 * inv, p1 = x1 * inv;
    int vv = x[gi];
    float pt = vv ? p1 : p0;
    pt = fminf(fmaxf(pt, 1e-7f), 1.0f);
    out[LOFF + (b*11 + 0)*Nn + n0] = -logf(pt);
    float* po = out + POFF + (((size_t)(b*Nn + n0))*11 + 0)*2;
    po[0] = p0; po[1] = p1;
    out[NOFF + (b*11 + 0)*Nn + n0] = sqrtf(ss);
    __syncthreads();

    uint32_t* dH = (uint32_t*)(e0 + (size_t)blockIdx.x * 128 * 64);
    for (int i = tid; i < 128*32; i += 128) {
        int row = i >> 5, q = i & 31;
        dH[i] = packf16(sE[row*65 + 2*q], sE[row*65 + 2*q + 1]);
    }
}

// ---------------------------------------------------------------------------
// Butterfly stage, half-split CTAs (hf=0 cn/even, hf=1 bn/odd), 256 thr,
// 2 CTAs/SM. All GEMM operands single-rounded fp16 (A, W1, W2); f32 accum.
// ---------------------------------------------------------------------------
__global__ void __launch_bounds__(THREADS, 2)
iter_mma(const __half* __restrict__ eHc, const int* __restrict__ v_cur,
         __half* __restrict__ eHn, int* __restrict__ v_next,
         const float* __restrict__ cnW1, const float* __restrict__ cnb1,
         const float* __restrict__ cnW2, const float* __restrict__ cnb2,
         const float* __restrict__ bnW1, const float* __restrict__ bnb1,
         const float* __restrict__ bnW2, const float* __restrict__ bnb2,
         const float* __restrict__ lab,  const float* __restrict__ llrW,
         const float* __restrict__ llrb, float* __restrict__ out, int t)
{
    extern __shared__ char sm[];
    const uint32_t sbase = su32(sm);
    float* sC2 = (float*)(sm + OS_C2);
    float* sB2 = (float*)(sm + OS_B2);
    float* sLW = (float*)(sm + OS_LW);
    float* sLB = (float*)(sm + OS_LB);
    uint8_t* sVx = (uint8_t*)(sm + OS_VX);
    uint8_t* sVe = (uint8_t*)(sm + OS_VE);

    const int tid  = threadIdx.x;
    const int wid  = tid >> 5, lane = tid & 31;
    const int wr   = wid;              // 8 warps: 16 rows each
    const int hf   = blockIdx.x & 1;   // 0: cn/even, 1: bn/odd
    const int lq   = lane & 3, lg   = lane >> 2;
    const int l15  = lane & 15;
    const int hi8  = lane >> 4;
    const int rx   = l15 & 7;

    // ---- stage weights -> smem (single fp16) ----
    const float* W1s = hf ? bnW1 : cnW1;
    const float* W2s = hf ? bnW2 : cnW2;
    const float* b1s = hf ? bnb1 : cnb1;
    const float* b2s = hf ? bnb2 : cnb2;
    for (int i = tid; i < 128*64; i += THREADS) {
        int k = i >> 6, f = i & 63;
        uint32_t o = swz128(k, f >> 3) + (f & 7)*2;
        *(__half*)(sm + OW1H + o) = __float2half_rn(W1s[k*64 + f]);
    }
    for (int i = tid; i < 64*64; i += THREADS) {
        int k = i >> 6, f = i & 63;
        uint32_t o = swz128(k, f >> 3) + (f & 7)*2;
        *(__half*)(sm + OW2H + o) = __float2half_rn(W2s[k*64 + f]);
    }
    if (tid < 64) sB2[tid] = b2s[tid];
    if (tid < 128) sLW[tid] = llrW[tid];
    if (tid < 2)   sLB[tid] = llrb[tid];
    if (tid < 128) {                   // sC2[j][f] = b1[f] (+ lab[j]·bnW1[128:192] if bn)
        int j = tid >> 6, f = tid & 63;
        float s = b1s[f];
        if (hf) {
            for (int k = 0; k < 64; k++) s = fmaf(lab[j*64 + k], bnW1[(128 + k)*64 + f], s);
        }
        sC2[j*64 + f] = s;
    }

    const int hs    = 1 << (t - 1);
    const int shl   = t - 1;
    const int jmask = hs - 1;
    const int mlo = 16*wr + lg, mhi = mlo + 8;
    const uint32_t aArow = (uint32_t)((16*wr + l15) << 8);
    uint32_t bswz[4];
    #pragma unroll
    for (int ntp = 0; ntp < 4; ntp++)
        bswz[ntp] = (uint32_t)((((2*ntp + hi8) ^ rx) & 7) << 4);

    const int tstep = (int)(gridDim.x >> 1);

    // ---- tile issue: cp.async gather of X + v loads ----
    auto issue = [&](int tile, int buf) {
        if (tile < NTILES) {
            const int pg0 = tile * TILE_P;
            const int b   = pg0 >> 9;
            const int pp0 = pg0 & 511;
            const __half* ehb = eHc + (size_t)b * (Nn*64);
            const uint32_t xh = sbase + buf*32768;
            #pragma unroll
            for (int ii = 0; ii < 8; ii++) {
                int i = tid + ii*THREADS;          // 2048 chunks
                int r = i >> 4, c16 = i & 15;
                int pp = pp0 + r;
                int oddn = ((pp >> shl) << t) + (pp & jmask);
                int n = oddn + ((c16 >> 3) ? hs : 0);
                cpa16(xh + swz(r, c16), (const char*)ehb + (size_t)n*128 + (c16 & 7)*16);
            }
            if (tid < 128) {
                int pp = pp0 + tid;
                int oddn = ((pp >> shl) << t) + (pp & jmask);
                int vo = v_cur[b*Nn + oddn];
                int ve = v_cur[b*Nn + oddn + hs];
                sVx[buf*128 + tid] = (uint8_t)((vo + ve) & 1);
                sVe[buf*128 + tid] = (uint8_t)ve;
            }
        }
        asm volatile("cp.async.commit_group;" ::: "memory");
    };

    int buf = 0;
    __syncthreads();
    issue((int)(blockIdx.x >> 1), 0);

    for (int tile = (int)(blockIdx.x >> 1); tile < NTILES; tile += tstep) {
        issue(tile + tstep, buf ^ 1);
        asm volatile("cp.async.wait_group 1;" ::: "memory");
        __syncthreads();

        const int pg0 = tile * TILE_P;
        const int b   = pg0 >> 9;
        const int pp0 = pg0 & 511;
        const uint32_t xbase = sbase + buf*32768;

        // ---- GEMM1: acc1[16 rows x 64 f] = X @ W1half^T (single pass) ----
        float acc1[8][4];
        #pragma unroll
        for (int i = 0; i < 8; i++)
            #pragma unroll
            for (int j = 0; j < 4; j++) acc1[i][j] = 0.f;

        #pragma unroll
        for (int kt = 0; kt < 8; kt++) {
            int ch = 2*kt + hi8;
            uint32_t ah[4];
            ldsm4(ah, xbase + aArow + ((((ch & 8) | ((ch ^ rx) & 7))) << 4));
            uint32_t brow = sbase + OW1H + (uint32_t)((16*kt + l15) << 7);
            #pragma unroll
            for (int ntp = 0; ntp < 4; ntp++) {
                uint32_t bh[4];
                ldsm4t(bh, brow + bswz[ntp]);
                mma16816(acc1[2*ntp],   ah, bh[0], bh[1]);
                mma16816(acc1[2*ntp+1], ah, bh[2], bh[3]);
            }
        }

        // ---- H epilogue: (bias + c_vx) + relu, cvt fp16 ----
        const int vxlo = sVx[buf*128 + mlo], vxhi = sVx[buf*128 + mhi];
        const float2* c2 = (const float2*)sC2;
        uint32_t pH0[8], pH1[8];
        #pragma unroll
        for (int nt = 0; nt < 8; nt++) {
            int q0 = 4*nt + lq;                 // float2 index within 32 per label
            float2 clo = c2[vxlo*32 + q0];
            float2 chi = c2[vxhi*32 + q0];
            float h00 = acc1[nt][0] + clo.x;
            float h01 = acc1[nt][1] + clo.y;
            float h10 = acc1[nt][2] + chi.x;
            float h11 = acc1[nt][3] + chi.y;
            pH0[nt] = packf16(fmaxf(h00, 0.f), fmaxf(h01, 0.f));
            pH1[nt] = packf16(fmaxf(h10, 0.f), fmaxf(h11, 0.f));
        }

        // ---- GEMM2: acc2 = H @ W2half^T (single pass) ----
        float acc2[8][4];
        #pragma unroll
        for (int i = 0; i < 8; i++)
            #pragma unroll
            for (int j = 0; j < 4; j++) acc2[i][j] = 0.f;

        #pragma unroll
        for (int kt = 0; kt < 4; kt++) {
            uint32_t a2[4] = {pH0[2*kt], pH1[2*kt], pH0[2*kt+1], pH1[2*kt+1]};
            uint32_t brow = sbase + OW2H + (uint32_t)((16*kt + l15) << 7);
            #pragma unroll
            for (int ntp = 0; ntp < 4; ntp++) {
                uint32_t bh[4];
                ldsm4t(bh, brow + bswz[ntp]);
                mma16816(acc2[2*ntp],   a2, bh[0], bh[1]);
                mma16816(acc2[2*ntp+1], a2, bh[2], bh[3]);
            }
        }

        // ---- output epilogue ----
        float pssL = 0.f, pl0L = 0.f, pl1L = 0.f;
        float pssH = 0.f, pl0H = 0.f, pl1H = 0.f;
        #pragma unroll
        for (int nt = 0; nt < 8; nt++) {
            int d0 = 8*nt + 2*lq;
            float e00 = acc2[nt][0] + sB2[d0];
            float e01 = acc2[nt][1] + sB2[d0+1];
            float e10 = acc2[nt][2] + sB2[d0];
            float e11 = acc2[nt][3] + sB2[d0+1];
            acc2[nt][0] = e00; acc2[nt][1] = e01;
            acc2[nt][2] = e10; acc2[nt][3] = e11;
            pssL = fmaf(e00,e00, fmaf(e01,e01, pssL));
            pssH = fmaf(e10,e10, fmaf(e11,e11, pssH));
            pl0L = fmaf(e00, sLW[2*d0],   fmaf(e01, sLW[2*d0+2], pl0L));
            pl1L = fmaf(e00, sLW[2*d0+1], fmaf(e01, sLW[2*d0+3], pl1L));
            pl0H = fmaf(e10, sLW[2*d0],   fmaf(e11, sLW[2*d0+2], pl0H));
            pl1H = fmaf(e10, sLW[2*d0+1], fmaf(e11, sLW[2*d0+3], pl1H));
        }
        #pragma unroll
        for (int off = 1; off <= 2; off <<= 1) {
            pssL += __shfl_xor_sync(0xffffffffu, pssL, off);
            pl0L += __shfl_xor_sync(0xffffffffu, pl0L, off);
            pl1L += __shfl_xor_sync(0xffffffffu, pl1L, off);
            pssH += __shfl_xor_sync(0xffffffffu, pssH, off);
            pl0H += __shfl_xor_sync(0xffffffffu, pl0H, off);
            pl1H += __shfl_xor_sync(0xffffffffu, pl1H, off);
        }
        if (lq == 0) {
            #pragma unroll
            for (int half = 0; half < 2; half++) {
                int p   = half ? mhi : mlo;
                float ss = half ? pssH : pssL;
                float l0 = (half ? pl0H : pl0L) + sLB[0];
                float l1 = (half ? pl1H : pl1L) + sLB[1];
                float m = fmaxf(l0, l1);
                float x0 = expf(l0 - m), x1 = expf(l1 - m);
                float inv = 1.f / (x0 + x1);
                float p0 = x0 * inv, p1 = x1 * inv;
                int vv = hf ? (int)sVe[buf*128 + p] : (int)sVx[buf*128 + p];
                float pt = vv ? p1 : p0;
                pt = fminf(fmaxf(pt, 1e-7f), 1.0f);
                int n = 2*(pp0 + p) + hf;
                out[LOFF + (b*11 + t)*Nn + n] = -logf(pt);
                float* po = out + POFF + (((size_t)(b*Nn + n))*11 + t)*2;
                po[0] = p0; po[1] = p1;
                out[NOFF + (b*11 + t)*Nn + n] = sqrtf(ss);
                v_next[b*Nn + n] = vv;
            }
        }
        {
            size_t rlo = ((size_t)b*Nn + 2*(pp0 + mlo) + hf)*64;
            size_t rhi = ((size_t)b*Nn + 2*(pp0 + mhi) + hf)*64;
            #pragma unroll
            for (int nt = 0; nt < 8; nt++) {
                int d0 = 8*nt + 2*lq;
                *(uint32_t*)(eHn + rlo + d0) = packf16(acc2[nt][0], acc2[nt][1]);
                *(uint32_t*)(eHn + rhi + d0) = packf16(acc2[nt][2], acc2[nt][3]);
            }
        }
        __syncthreads();
        buf ^= 1;
    }
}

// ---------------------------------------------------------------------------
extern "C" void kernel_launch(void* const* d_in, const int* in_sizes, int n_in,
                              void* d_out, int out_size)
{
    const int*   x     = (const int*)  d_in[0];
    const float* y     = (const float*)d_in[1];
    const float* embW  = (const float*)d_in[2];
    const float* embB  = (const float*)d_in[3];
    const float* lab   = (const float*)d_in[4];
    const float* cnW1  = (const float*)d_in[5];
    const float* cnb1  = (const float*)d_in[6];
    const float* cnW2  = (const float*)d_in[7];
    const float* cnb2  = (const float*)d_in[8];
    const float* bnW1  = (const float*)d_in[9];
    const float* bnb1  = (const float*)d_in[10];
    const float* bnW2  = (const float*)d_in[11];
    const float* bnb2  = (const float*)d_in[12];
    const float* llrW  = (const float*)d_in[13];
    const float* llrb  = (const float*)d_in[14];
    float* out = (float*)d_out;

    __half *eA, *eB; int *vA, *vB;
    cudaGetSymbolAddress((void**)&eA, g_eA);
    cudaGetSymbolAddress((void**)&eB, g_eB);
    cudaGetSymbolAddress((void**)&vA, g_vA);
    cudaGetSymbolAddress((void**)&vB, g_vB);

    int smcount = 148;
    cudaDeviceGetAttribute(&smcount, cudaDevAttrMultiProcessorCount, 0);
    cudaFuncSetAttribute(iter_mma, cudaFuncAttributeMaxDynamicSharedMemorySize, SMEM_BYTES);

    stage0_kernel<<<(Bb*Nn)/128, 128>>>(x, y, embW, embB, llrW, llrb, eA, out);

    for (int t = 1; t <= 10; t++) {
        const __half* ec = (t & 1) ? eA : eB;
        __half*       en = (t & 1) ? eB : eA;
        const int* vc = (t == 1) ? x : ((t & 1) ? vB : vA);
        int*       vn = (t & 1) ? vA : vB;
        iter_mma<<<2*smcount, THREADS, SMEM_BYTES>>>(
            ec, vc, en, vn,
            cnW1, cnb1, cnW2, cnb2,
            bnW1, bnb1, bnW2, bnb2,
            lab, llrW, llrb, out, t);
    }
}

// round 15
// speedup vs baseline: 6.3522x; 1.2770x over previous
#include <cuda_runtime.h>
#include <cuda_fp16.h>
#include <math.h>
#include <stdint.h>

#define Bb 256
#define Nn 1024
#define THREADS 512

// output buffer offsets (floats)
#define LOFF 0
#define POFF (Bb*11*Nn)
#define NOFF (POFF + Bb*Nn*11*2)

// smem byte offsets
#define OE   0                 // e: 1024 rows x 128B (fp16, swizzled 16B chunks)
#define OW1  131072            // W1: cn half 16KB, bn half 16KB
#define OW2  163840            // W2: cn 8KB, bn 8KB
#define OFL  180224
#define OS_LW  (OFL + 0)       // 128 floats
#define OS_B2  (OFL + 512)     // 2 x 64 floats
#define OS_C2C (OFL + 1024)    // 64 floats  (cn: b1)
#define OS_C2B (OFL + 1280)    // 2 x 64 floats (bn: b1 + c_j)
#define OS_LB  (OFL + 1792)    // 2 floats
#define OS_V   (OFL + 1800)    // 1024 bytes
#define SMEM_BYTES (OFL + 2880)

// ---------------------------------------------------------------------------
__device__ __forceinline__ uint32_t su32(const void* p) {
    uint32_t a;
    asm("{ .reg .u64 t; cvta.to.shared.u64 t, %1; cvt.u32.u64 %0, t; }" : "=r"(a) : "l"(p));
    return a;
}
__device__ __forceinline__ void ldsm4(uint32_t* r, uint32_t addr) {
    asm volatile("ldmatrix.sync.aligned.m8n8.x4.shared.b16 {%0,%1,%2,%3}, [%4];"
        : "=r"(r[0]), "=r"(r[1]), "=r"(r[2]), "=r"(r[3]) : "r"(addr));
}
__device__ __forceinline__ void ldsm4t(uint32_t* r, uint32_t addr) {
    asm volatile("ldmatrix.sync.aligned.m8n8.x4.trans.shared.b16 {%0,%1,%2,%3}, [%4];"
        : "=r"(r[0]), "=r"(r[1]), "=r"(r[2]), "=r"(r[3]) : "r"(addr));
}
__device__ __forceinline__ void mma16816(float* c, const uint32_t* a, uint32_t b0, uint32_t b1) {
    asm volatile("mma.sync.aligned.m16n8k16.row.col.f32.f16.f16.f32 "
        "{%0,%1,%2,%3}, {%4,%5,%6,%7}, {%8,%9}, {%0,%1,%2,%3};"
        : "+f"(c[0]), "+f"(c[1]), "+f"(c[2]), "+f"(c[3])
        : "r"(a[0]), "r"(a[1]), "r"(a[2]), "r"(a[3]), "r"(b0), "r"(b1));
}
__device__ __forceinline__ uint32_t packf16(float a, float b) {
    __half2 t = __floats2half2_rn(a, b);
    return *(uint32_t*)&t;
}
__device__ __forceinline__ void sts32(uint32_t addr, uint32_t v) {
    asm volatile("st.shared.b32 [%0], %1;" :: "r"(addr), "r"(v) : "memory");
}
__device__ __forceinline__ void sts128(uint32_t addr, uint32_t a, uint32_t b, uint32_t c, uint32_t d) {
    asm volatile("st.shared.v4.b32 [%0], {%1,%2,%3,%4};" :: "r"(addr), "r"(a), "r"(b), "r"(c), "r"(d) : "memory");
}
// weight swizzle: 128B rows, 8 chunks of 16B
__device__ __forceinline__ uint32_t swz128(int r, int c16) {
    return (uint32_t)((r << 7) + (((c16 ^ r) & 7) << 4));
}

// ---------------------------------------------------------------------------
// Persistent per-sequence kernel: all 11 output stages, e held in smem.
// In-place butterfly: physical layout at stage t = logical with low (t-1)
// bits bit-reversed. 16 warps = 8 (M, 16 rows) x 2 (cn/bn half).
// ---------------------------------------------------------------------------
__global__ void __launch_bounds__(THREADS, 1)
npd_kernel(const int* __restrict__ x, const float* __restrict__ y,
           const float* __restrict__ embW, const float* __restrict__ embB,
           const float* __restrict__ lab,
           const float* __restrict__ cnW1, const float* __restrict__ cnb1,
           const float* __restrict__ cnW2, const float* __restrict__ cnb2,
           const float* __restrict__ bnW1, const float* __restrict__ bnb1,
           const float* __restrict__ bnW2, const float* __restrict__ bnb2,
           const float* __restrict__ llrW, const float* __restrict__ llrb,
           float* __restrict__ out)
{
    extern __shared__ char sm[];
    const uint32_t sbase = su32(sm);
    float* sLW  = (float*)(sm + OS_LW);
    float* sB2  = (float*)(sm + OS_B2);
    float* sC2c = (float*)(sm + OS_C2C);
    float* sC2b = (float*)(sm + OS_C2B);
    float* sLB  = (float*)(sm + OS_LB);
    uint8_t* sV = (uint8_t*)(sm + OS_V);

    const int tid = threadIdx.x;
    const int wid = tid >> 5, lane = tid & 31;
    const int wr  = wid & 7,  wc   = wid >> 3;     // 8 M-warps x 2 halves
    const int lq  = lane & 3, lg   = lane >> 2;
    const int l15 = lane & 15;
    const int hi8 = lane >> 4;
    const int rx  = l15 & 7;
    const int b   = blockIdx.x;

    // ---- stage weights -> smem (once per kernel) ----
    for (int i = tid; i < 128*64; i += THREADS) {
        int k = i >> 6, f = i & 63;
        uint32_t o = swz128(k, f >> 3) + (f & 7)*2;
        *(__half*)(sm + OW1 + o)         = __float2half_rn(cnW1[k*64 + f]);
        *(__half*)(sm + OW1 + 16384 + o) = __float2half_rn(bnW1[k*64 + f]);
    }
    for (int i = tid; i < 64*64; i += THREADS) {
        int k = i >> 6, f = i & 63;
        uint32_t o = swz128(k, f >> 3) + (f & 7)*2;
        *(__half*)(sm + OW2 + o)        = __float2half_rn(cnW2[k*64 + f]);
        *(__half*)(sm + OW2 + 8192 + o) = __float2half_rn(bnW2[k*64 + f]);
    }
    if (tid < 128) sLW[tid] = llrW[tid];
    if (tid < 2)   sLB[tid] = llrb[tid];
    if (tid < 64)  sC2c[tid] = cnb1[tid];
    if (tid < 128) {                 // bn: b1 + lab[j]·bnW1[128:192,:]
        int j = tid >> 6, f = tid & 63;
        float s = bnb1[f];
        for (int k = 0; k < 64; k++) s = fmaf(lab[j*64 + k], bnW1[(128 + k)*64 + f], s);
        sC2b[tid] = s;
    }
    if (tid < 128) sB2[tid] = (tid < 64) ? cnb2[tid] : bnb2[tid - 64];
    __syncthreads();

    // ---- stage 0: e0 = y @ embW + embB, stats, store rows to smem ----
    {
        const float* yb = y + (size_t)b * 2048;
        const int*   xb = x + b*1024;
        #pragma unroll
        for (int rep = 0; rep < 2; rep++) {
            int n = tid + rep*512;
            float y0 = yb[2*n], y1 = yb[2*n + 1];
            float ev[64];
            float ss = 0.f, l0 = sLB[0], l1 = sLB[1];
            #pragma unroll
            for (int d = 0; d < 64; d++) {
                float e = fmaf(y0, embW[d], fmaf(y1, embW[64 + d], embB[d]));
                ev[d] = e;
                ss = fmaf(e, e, ss);
                l0 = fmaf(e, sLW[2*d], l0);
                l1 = fmaf(e, sLW[2*d+1], l1);
            }
            float m = fmaxf(l0, l1);
            float x0 = expf(l0 - m), x1 = expf(l1 - m);
            float inv = 1.f / (x0 + x1);
            float p0 = x0 * inv, p1 = x1 * inv;
            int vv = xb[n];
            float pt = vv ? p1 : p0;
            pt = fminf(fmaxf(pt, 1e-7f), 1.0f);
            out[LOFF + (b*11 + 0)*Nn + n] = -logf(pt);
            float* po = out + POFF + (((size_t)(b*Nn + n))*11 + 0)*2;
            po[0] = p0; po[1] = p1;
            out[NOFF + (b*11 + 0)*Nn + n] = sqrtf(ss);
            sV[n] = (uint8_t)vv;
            uint32_t rb = sbase + OE + (uint32_t)(n << 7);
            #pragma unroll
            for (int c = 0; c < 8; c++) {
                uint32_t a0 = packf16(ev[8*c+0], ev[8*c+1]);
                uint32_t a1 = packf16(ev[8*c+2], ev[8*c+3]);
                uint32_t a2 = packf16(ev[8*c+4], ev[8*c+5]);
                uint32_t a3 = packf16(ev[8*c+6], ev[8*c+7]);
                sts128(rb + (uint32_t)(((c ^ n) & 7) << 4), a0, a1, a2, a3);
            }
        }
    }
    __syncthreads();

    uint32_t bswz[4];
    #pragma unroll
    for (int ntp = 0; ntp < 4; ntp++)
        bswz[ntp] = (uint32_t)((((2*ntp + hi8) ^ rx) & 7) << 4);

    // ---- stages 1..10, in-place in smem ----
    for (int t = 1; t <= 10; t++) {
        const int hs = 1 << (t - 1);
        for (int tile = 0; tile < 4; tile++) {
            const int g0 = tile << 7;

            // per-lane A rows (physical)
            int gA = g0 + 16*wr + l15;
            int pa = ((gA >> (t-1)) << t) | (gA & (hs - 1));
            int pb = pa + hs;
            uint32_t paB = sbase + OE + (uint32_t)(pa << 7);
            uint32_t pbB = sbase + OE + (uint32_t)(pb << 7);

            // ---- GEMM1: acc1[16 rows x 64 f] = [e_a|e_b] @ W1half^T ----
            float acc1[8][4];
            #pragma unroll
            for (int i = 0; i < 8; i++)
                #pragma unroll
                for (int j = 0; j < 4; j++) acc1[i][j] = 0.f;

            #pragma unroll
            for (int kt = 0; kt < 8; kt++) {
                int c = 2*(kt & 3) + hi8;
                uint32_t arow = (kt < 4) ? (paB + (uint32_t)(((c ^ pa) & 7) << 4))
                                         : (pbB + (uint32_t)(((c ^ pb) & 7) << 4));
                uint32_t ah[4];
                ldsm4(ah, arow);
                uint32_t brow = sbase + OW1 + (uint32_t)(wc << 14) + (uint32_t)((16*kt + l15) << 7);
                #pragma unroll
                for (int ntp = 0; ntp < 4; ntp++) {
                    uint32_t bh[4];
                    ldsm4t(bh, brow + bswz[ntp]);
                    mma16816(acc1[2*ntp],   ah, bh[0], bh[1]);
                    mma16816(acc1[2*ntp+1], ah, bh[2], bh[3]);
                }
            }

            // per-thread owned pair rows + v (read BEFORE barrier)
            int gml = g0 + 16*wr + lg, gmh = gml + 8;
            int paml = ((gml >> (t-1)) << t) | (gml & (hs - 1)); int pbml = paml + hs;
            int pamh = ((gmh >> (t-1)) << t) | (gmh & (hs - 1)); int pbmh = pamh + hs;
            int vbl = sV[pbml], vbh = sV[pbmh];
            int vxl = (sV[paml] + vbl) & 1;
            int vxh = (sV[pamh] + vbh) & 1;
            __syncthreads();          // all GEMM1 reads done before any writes

            // ---- H epilogue: (b1 [+ c_vx]) + relu -> fp16 ----
            const float2* c2b = (const float2*)sC2b;
            const float2* c2c = (const float2*)sC2c;
            uint32_t pH0[8], pH1[8];
            #pragma unroll
            for (int nt = 0; nt < 8; nt++) {
                int q0 = 4*nt + lq;
                float2 clo = wc ? c2b[vxl*32 + q0] : c2c[q0];
                float2 chi = wc ? c2b[vxh*32 + q0] : c2c[q0];
                float h00 = acc1[nt][0] + clo.x;
                float h01 = acc1[nt][1] + clo.y;
                float h10 = acc1[nt][2] + chi.x;
                float h11 = acc1[nt][3] + chi.y;
                pH0[nt] = packf16(fmaxf(h00, 0.f), fmaxf(h01, 0.f));
                pH1[nt] = packf16(fmaxf(h10, 0.f), fmaxf(h11, 0.f));
            }

            // ---- GEMM2: acc2 = H @ W2half^T ----
            float acc2[8][4];
            #pragma unroll
            for (int i = 0; i < 8; i++)
                #pragma unroll
                for (int j = 0; j < 4; j++) acc2[i][j] = 0.f;

            #pragma unroll
            for (int kt = 0; kt < 4; kt++) {
                uint32_t a2[4] = {pH0[2*kt], pH1[2*kt], pH0[2*kt+1], pH1[2*kt+1]};
                uint32_t brow = sbase + OW2 + (uint32_t)(wc << 13) + (uint32_t)((16*kt + l15) << 7);
                #pragma unroll
                for (int ntp = 0; ntp < 4; ntp++) {
                    uint32_t bh[4];
                    ldsm4t(bh, brow + bswz[ntp]);
                    mma16816(acc2[2*ntp],   a2, bh[0], bh[1]);
                    mma16816(acc2[2*ntp+1], a2, bh[2], bh[3]);
                }
            }

            // ---- output epilogue: bias, stats, gmem out, smem e'/v' ----
            float pssL = 0.f, pl0L = 0.f, pl1L = 0.f;
            float pssH = 0.f, pl0H = 0.f, pl1H = 0.f;
            #pragma unroll
            for (int nt = 0; nt < 8; nt++) {
                int d0 = 8*nt + 2*lq;
                float e00 = acc2[nt][0] + sB2[wc*64 + d0];
                float e01 = acc2[nt][1] + sB2[wc*64 + d0+1];
                float e10 = acc2[nt][2] + sB2[wc*64 + d0];
                float e11 = acc2[nt][3] + sB2[wc*64 + d0+1];
                acc2[nt][0] = e00; acc2[nt][1] = e01;
                acc2[nt][2] = e10; acc2[nt][3] = e11;
                pssL = fmaf(e00,e00, fmaf(e01,e01, pssL));
                pssH = fmaf(e10,e10, fmaf(e11,e11, pssH));
                pl0L = fmaf(e00, sLW[2*d0],   fmaf(e01, sLW[2*d0+2], pl0L));
                pl1L = fmaf(e00, sLW[2*d0+1], fmaf(e01, sLW[2*d0+3], pl1L));
                pl0H = fmaf(e10, sLW[2*d0],   fmaf(e11, sLW[2*d0+2], pl0H));
                pl1H = fmaf(e10, sLW[2*d0+1], fmaf(e11, sLW[2*d0+3], pl1H));
            }
            #pragma unroll
            for (int off = 1; off <= 2; off <<= 1) {
                pssL += __shfl_xor_sync(0xffffffffu, pssL, off);
                pl0L += __shfl_xor_sync(0xffffffffu, pl0L, off);
                pl1L += __shfl_xor_sync(0xffffffffu, pl1L, off);
                pssH += __shfl_xor_sync(0xffffffffu, pssH, off);
                pl0H += __shfl_xor_sync(0xffffffffu, pl0H, off);
                pl1H += __shfl_xor_sync(0xffffffffu, pl1H, off);
            }
            if (lq == 0) {
                #pragma unroll
                for (int half = 0; half < 2; half++) {
                    int g_  = half ? gmh : gml;
                    float ss = half ? pssH : pssL;
                    float l0 = (half ? pl0H : pl0L) + sLB[0];
                    float l1 = (half ? pl1H : pl1L) + sLB[1];
                    float m = fmaxf(l0, l1);
                    float x0 = expf(l0 - m), x1 = expf(l1 - m);
                    float inv = 1.f / (x0 + x1);
                    float p0 = x0 * inv, p1 = x1 * inv;
                    int vv = half ? (wc ? vbh : vxh) : (wc ? vbl : vxl);
                    float pt = vv ? p1 : p0;
                    pt = fminf(fmaxf(pt, 1e-7f), 1.0f);
                    unsigned m_ = (unsigned)(g_ & (hs - 1));
                    unsigned j_ = (t > 1) ? (__brev(m_) >> (33 - t)) : 0u;
                    int pp_ = ((g_ >> (t-1)) << (t-1)) | (int)j_;
                    int n = 2*pp_ + wc;
                    out[LOFF + (b*11 + t)*Nn + n] = -logf(pt);
                    float* po = out + POFF + (((size_t)(b*Nn + n))*11 + t)*2;
                    po[0] = p0; po[1] = p1;
                    out[NOFF + (b*11 + t)*Nn + n] = sqrtf(ss);
                }
                // v': even (cn) rows get vxor at phys pa; odd (bn) get ve at phys pb
                if (wc) { sV[pbml] = (uint8_t)vbl; sV[pbmh] = (uint8_t)vbh; }
                else    { sV[paml] = (uint8_t)vxl; sV[pamh] = (uint8_t)vxh; }
            }
            // e' write-back, in place: cn -> pa rows, bn -> pb rows
            {
                int wrl = wc ? pbml : paml;
                int wrh = wc ? pbmh : pamh;
                uint32_t bl  = sbase + OE + (uint32_t)(wrl << 7);
                uint32_t bh_ = sbase + OE + (uint32_t)(wrh << 7);
                #pragma unroll
                for (int nt = 0; nt < 8; nt++) {
                    sts32(bl  + (uint32_t)(((nt ^ wrl) & 7) << 4) + 4*lq,
                          packf16(acc2[nt][0], acc2[nt][1]));
                    sts32(bh_ + (uint32_t)(((nt ^ wrh) & 7) << 4) + 4*lq,
                          packf16(acc2[nt][2], acc2[nt][3]));
                }
            }
        }
        __syncthreads();   // stage complete before next stage reads
    }
}

// ---------------------------------------------------------------------------
extern "C" void kernel_launch(void* const* d_in, const int* in_sizes, int n_in,
                              void* d_out, int out_size)
{
    const int*   x     = (const int*)  d_in[0];
    const float* y     = (const float*)d_in[1];
    const float* embW  = (const float*)d_in[2];
    const float* embB  = (const float*)d_in[3];
    const float* lab   = (const float*)d_in[4];
    const float* cnW1  = (const float*)d_in[5];
    const float* cnb1  = (const float*)d_in[6];
    const float* cnW2  = (const float*)d_in[7];
    const float* cnb2  = (const float*)d_in[8];
    const float* bnW1  = (const float*)d_in[9];
    const float* bnb1  = (const float*)d_in[10];
    const float* bnW2  = (const float*)d_in[11];
    const float* bnb2  = (const float*)d_in[12];
    const float* llrW  = (const float*)d_in[13];
    const float* llrb  = (const float*)d_in[14];
    float* out = (float*)d_out;

    cudaFuncSetAttribute(npd_kernel, cudaFuncAttributeMaxDynamicSharedMemorySize, SMEM_BYTES);
    npd_kernel<<<Bb, THREADS, SMEM_BYTES>>>(
        x, y, embW, embB, lab,
        cnW1, cnb1, cnW2, cnb2,
        bnW1, bnb1, bnW2, bnb2,
        llrW, llrb, out);
}